// round 1
// baseline (speedup 1.0000x reference)
#include <cuda_runtime.h>
#include <math.h>

#define EPSV 1e-5f

// ---- dims ----
#define BB   16
#define CC   32
#define FF   64
#define TT   1024
#define LL   1024
#define HH   512
#define PP   256
#define FEAT2 2048
#define DD   1024
#define NROWS (LL*BB)   // 16384

// ---- scratch (device globals; allocation-free) ----
__device__ float g_bufA[BB*CC*FF*TT];      // 33.55M
__device__ float g_bufB[BB*CC*FF*TT];      // 33.55M
__device__ float g_xn[NROWS*FEAT2];        // 33.55M
__device__ float g_tmp[NROWS*PP];          // 4.19M
__device__ float g_U[NROWS*4096];          // 67.1M
__device__ float g_sa[NROWS*DD];           // 16.78M
__device__ float g_sb[NROWS*DD];           // 16.78M
__device__ float g_wT[CC*CC*9];            // folded+transposed conv weights
__device__ float g_bias2[CC];

// ============================================================
// conv0: x(16,1,128,2048) -> out(16,32,64,1024), 3x3 s2 p1, +bias
// ============================================================
__global__ void conv0_kernel(const float* __restrict__ x,
                             const float* __restrict__ w,
                             const float* __restrict__ cb,
                             float* __restrict__ out) {
    __shared__ float ws[288];   // [j][co]
    __shared__ float bs[32];
    int tid = threadIdx.x;
    for (int i = tid; i < 288; i += 256) {
        int co = i / 9, j = i % 9;
        ws[j*32 + co] = w[i];
    }
    if (tid < 32) bs[tid] = cb[tid];
    __syncthreads();

    int to = blockIdx.x * 256 + tid;   // 0..1023
    int fo = blockIdx.y;               // 0..63
    int b  = blockIdx.z;               // 0..15

    float acc[32];
#pragma unroll
    for (int q = 0; q < 32; q++) acc[q] = bs[q];

#pragma unroll
    for (int df = 0; df < 3; df++) {
        int xi = 2*fo + df - 1;
        if (xi < 0 || xi >= 128) continue;
#pragma unroll
        for (int dt = 0; dt < 3; dt++) {
            int ti = 2*to + dt - 1;
            if (ti < 0 || ti >= 2048) continue;
            float v = x[((size_t)b*128 + xi)*2048 + ti];
            int j = df*3 + dt;
#pragma unroll
            for (int q = 0; q < 8; q++) {
                float4 w4 = *(const float4*)&ws[j*32 + q*4];
                acc[q*4+0] = fmaf(v, w4.x, acc[q*4+0]);
                acc[q*4+1] = fmaf(v, w4.y, acc[q*4+1]);
                acc[q*4+2] = fmaf(v, w4.z, acc[q*4+2]);
                acc[q*4+3] = fmaf(v, w4.w, acc[q*4+3]);
            }
        }
    }
    size_t ob = ((size_t)b*32)*65536 + (size_t)fo*1024 + to;
#pragma unroll
    for (int co = 0; co < 32; co++)
        out[ob + (size_t)co*65536] = acc[co];
}

// ============================================================
// prep: fold BN into conv weights, transpose to [(ci*9+j)][co]
//   wT = w * scale[co];  bias2 = beta + (cb - m)*scale
// ============================================================
__global__ void prep_conv_kernel(const float* __restrict__ w,
                                 const float* __restrict__ cb,
                                 const float* __restrict__ g,
                                 const float* __restrict__ beta,
                                 const float* __restrict__ m,
                                 const float* __restrict__ v,
                                 float* __restrict__ wT,
                                 float* __restrict__ bias2) {
    int tid = blockIdx.x * blockDim.x + threadIdx.x;
    if (tid < 9216) {
        int co = tid / 288;
        int r  = tid % 288;                 // ci*9 + j
        float scale = g[co] * rsqrtf(v[co] + EPSV);
        wT[r*32 + co] = w[tid] * scale;
    }
    if (tid < 32) {
        float scale = g[tid] * rsqrtf(v[tid] + EPSV);
        bias2[tid] = beta[tid] + (cb[tid] - m[tid]) * scale;
    }
}

// ============================================================
// residual conv: out = relu( conv3x3(in)*bn + bias2 [+ res] )
// each thread: one (b,f,t), all 32 output channels
// ============================================================
__global__ void resconv_kernel(const float* __restrict__ in,
                               const float* __restrict__ wT,
                               const float* __restrict__ bias2,
                               const float* __restrict__ res,
                               float* __restrict__ out) {
    __shared__ float ws[9216];
    __shared__ float bs[32];
    int tid = threadIdx.x;
    for (int i = tid; i < 2304; i += 256)
        ((float4*)ws)[i] = ((const float4*)wT)[i];
    if (tid < 32) bs[tid] = bias2[tid];
    __syncthreads();

    int t = blockIdx.x * 256 + tid;
    int f = blockIdx.y;
    int b = blockIdx.z;

    float acc[32];
#pragma unroll
    for (int q = 0; q < 32; q++) acc[q] = bs[q];

    bool fm = f > 0, fp = f < 63, tm = t > 0, tp = t < 1023;

    for (int ci = 0; ci < 32; ci++) {
        size_t base = (((size_t)b*32 + ci)*64 + f)*1024 + t;
        float xv[9];
        xv[0] = (fm && tm) ? in[base - 1024 - 1] : 0.f;
        xv[1] =  fm        ? in[base - 1024]     : 0.f;
        xv[2] = (fm && tp) ? in[base - 1024 + 1] : 0.f;
        xv[3] =  tm        ? in[base - 1]        : 0.f;
        xv[4] =              in[base];
        xv[5] =  tp        ? in[base + 1]        : 0.f;
        xv[6] = (fp && tm) ? in[base + 1024 - 1] : 0.f;
        xv[7] =  fp        ? in[base + 1024]     : 0.f;
        xv[8] = (fp && tp) ? in[base + 1024 + 1] : 0.f;

        const float* wr = ws + ci*288;
#pragma unroll
        for (int j = 0; j < 9; j++) {
            float v = xv[j];
#pragma unroll
            for (int q = 0; q < 8; q++) {
                float4 w4 = *(const float4*)&wr[j*32 + q*4];
                acc[q*4+0] = fmaf(v, w4.x, acc[q*4+0]);
                acc[q*4+1] = fmaf(v, w4.y, acc[q*4+1]);
                acc[q*4+2] = fmaf(v, w4.z, acc[q*4+2]);
                acc[q*4+3] = fmaf(v, w4.w, acc[q*4+3]);
            }
        }
    }

    size_t ob = (((size_t)b*32)*64 + f)*1024 + t;
    bool hasres = (res != nullptr);
#pragma unroll
    for (int co = 0; co < 32; co++) {
        float vv = acc[co];
        if (hasres) vv += res[ob + (size_t)co*65536];
        out[ob + (size_t)co*65536] = fmaxf(vv, 0.f);
    }
}

// ============================================================
// transpose: (b, cf=2048, t=1024) -> s[t][b][cf]
// ============================================================
__global__ void transpose_kernel(const float* __restrict__ in,
                                 float* __restrict__ out) {
    __shared__ float tile[32][33];
    int b  = blockIdx.z;
    int t0 = blockIdx.x * 32;
    int c0 = blockIdx.y * 32;
    int tx = threadIdx.x, ty = threadIdx.y;  // (32,8)
#pragma unroll
    for (int i = 0; i < 4; i++)
        tile[ty + 8*i][tx] = in[((size_t)b*2048 + c0 + ty + 8*i)*1024 + t0 + tx];
    __syncthreads();
#pragma unroll
    for (int i = 0; i < 4; i++)
        out[(((size_t)(t0 + ty + 8*i))*16 + b)*2048 + c0 + tx] = tile[tx][ty + 8*i];
}

// ============================================================
// LayerNorm per row (W = 2048 or 1024), 256 threads/row
// ============================================================
__global__ void ln_kernel(const float* __restrict__ in,
                          const float* __restrict__ g,
                          const float* __restrict__ bb,
                          float* __restrict__ out, int W) {
    int row = blockIdx.x;
    int tid = threadIdx.x;
    const float* x = in + (size_t)row * W;

    float s = 0.f, s2 = 0.f;
    for (int i = tid*4; i < W; i += 1024) {
        float4 v = *(const float4*)(x + i);
        s  += v.x + v.y + v.z + v.w;
        s2 += v.x*v.x + v.y*v.y + v.z*v.z + v.w*v.w;
    }
    __shared__ float rs[256], rs2[256];
    rs[tid] = s; rs2[tid] = s2;
    __syncthreads();
    for (int o = 128; o > 0; o >>= 1) {
        if (tid < o) { rs[tid] += rs[tid+o]; rs2[tid] += rs2[tid+o]; }
        __syncthreads();
    }
    float mean = rs[0] / W;
    float var  = rs2[0] / W - mean * mean;
    float inv  = rsqrtf(var + EPSV);

    float* o = out + (size_t)row * W;
    for (int i = tid*4; i < W; i += 1024) {
        float4 v  = *(const float4*)(x + i);
        float4 gg = *(const float4*)(g + i);
        float4 bv = *(const float4*)(bb + i);
        float4 r;
        r.x = (v.x - mean)*inv*gg.x + bv.x;
        r.y = (v.y - mean)*inv*gg.y + bv.y;
        r.z = (v.z - mean)*inv*gg.z + bv.z;
        r.w = (v.w - mean)*inv*gg.w + bv.w;
        *(float4*)(o + i) = r;
    }
}

// ============================================================
// SGEMM: C[M,N] = A[M,K] @ B[K,N], row-major fp32
// BM=128, BN=64, BK=16; 256 threads, 8x4 per thread
// M%128==0, N%64==0, K%16==0 guaranteed
// ============================================================
__global__ void sgemm_kernel(const float* __restrict__ A,
                             const float* __restrict__ Bm,
                             float* __restrict__ Cm,
                             int M, int N, int K) {
    __shared__ float As[16][128];
    __shared__ float Bs[16][64];
    int tid = threadIdx.x;
    int m0 = blockIdx.y * 128, n0 = blockIdx.x * 64;
    int ty = tid / 16, tx = tid % 16;

    float acc[8][4];
#pragma unroll
    for (int i = 0; i < 8; i++)
#pragma unroll
        for (int j = 0; j < 4; j++) acc[i][j] = 0.f;

    for (int k0 = 0; k0 < K; k0 += 16) {
#pragma unroll
        for (int l = 0; l < 2; l++) {
            int id = tid + l*256;
            int r = id >> 2, c4 = (id & 3) * 4;
            float4 v = *(const float4*)&A[(size_t)(m0 + r)*K + k0 + c4];
            As[c4+0][r] = v.x; As[c4+1][r] = v.y;
            As[c4+2][r] = v.z; As[c4+3][r] = v.w;
        }
        {
            int r = tid >> 4, cc = (tid & 15) * 4;
            *(float4*)&Bs[r][cc] = *(const float4*)&Bm[(size_t)(k0 + r)*N + n0 + cc];
        }
        __syncthreads();
#pragma unroll
        for (int kk = 0; kk < 16; kk++) {
            float4 a0 = *(const float4*)&As[kk][ty*8];
            float4 a1 = *(const float4*)&As[kk][ty*8 + 4];
            float4 bv = *(const float4*)&Bs[kk][tx*4];
            float a[8] = {a0.x,a0.y,a0.z,a0.w,a1.x,a1.y,a1.z,a1.w};
            float bq[4] = {bv.x,bv.y,bv.z,bv.w};
#pragma unroll
            for (int i = 0; i < 8; i++)
#pragma unroll
                for (int j = 0; j < 4; j++)
                    acc[i][j] = fmaf(a[i], bq[j], acc[i][j]);
        }
        __syncthreads();
    }
#pragma unroll
    for (int i = 0; i < 8; i++) {
        float4 v = {acc[i][0], acc[i][1], acc[i][2], acc[i][3]};
        *(float4*)&Cm[(size_t)(m0 + ty*8 + i)*N + n0 + tx*4] = v;
    }
}

// ============================================================
// SRU recurrence. U rows (t*16+b) of width 2*KK*512.
// thread = (d, b, j). out rows width 1024 (dir concat).
// ============================================================
__device__ __forceinline__ float sigmf(float x) {
    return 1.f / (1.f + __expf(-x));
}

template <int KK>
__global__ void sru_kernel(const float* __restrict__ U,
                           const float* __restrict__ xn,
                           const float* __restrict__ vc,
                           const float* __restrict__ bias,
                           float* __restrict__ out) {
    int idx = blockIdx.x * blockDim.x + threadIdx.x;  // 0..16383
    int j = idx & 511;
    int b = (idx >> 9) & 15;
    int d = idx >> 13;

    float vf = vc[d*1024 + j],       vr = vc[d*1024 + 512 + j];
    float bf = bias[d*1024 + j],     br = bias[d*1024 + 512 + j];

    const int RW = 2*KK*512;
    int colbase = b*RW + d*KK*512 + j;
    int obase   = b*1024 + d*512 + j;

    float c = 0.f;
#pragma unroll 2
    for (int s = 0; s < 1024; s++) {
        int t = d ? (1023 - s) : s;
        size_t off = (size_t)t*16*RW + colbase;
        float a0 = U[off];
        float a1 = U[off + 512];
        float a2 = U[off + 1024];
        float rx = (KK == 4) ? U[off + 1536]
                             : xn[(size_t)t*16*1024 + obase];
        float f = sigmf(fmaf(vf, c, a1) + bf);
        c = fmaf(f, c - a0, a0);
        float r = sigmf(fmaf(vr, c, a2) + br);
        out[(size_t)t*16*1024 + obase] = fmaf(r, c - rx, rx);
    }
}

// ============================================================
// final: per row (t*16+b): LN over 1024 then @ cls_w(1024,30)
// out[b][t][k]
// ============================================================
__global__ void final_kernel(const float* __restrict__ s,
                             const float* __restrict__ g,
                             const float* __restrict__ bb,
                             const float* __restrict__ cw,
                             float* __restrict__ out) {
    int row = blockIdx.x;       // t*16 + b
    int t = row >> 4, b = row & 15;
    int tid = threadIdx.x;      // 256
    const float* x = s + (size_t)row * 1024;

    float4 v4 = *(const float4*)(x + tid*4);
    float sm = v4.x + v4.y + v4.z + v4.w;
    float s2 = v4.x*v4.x + v4.y*v4.y + v4.z*v4.z + v4.w*v4.w;

    __shared__ float rs[256], rs2[256];
    rs[tid] = sm; rs2[tid] = s2;
    __syncthreads();
    for (int o = 128; o > 0; o >>= 1) {
        if (tid < o) { rs[tid] += rs[tid+o]; rs2[tid] += rs2[tid+o]; }
        __syncthreads();
    }
    float mean = rs[0] * (1.f/1024.f);
    float var  = rs2[0] * (1.f/1024.f) - mean*mean;
    float inv  = rsqrtf(var + EPSV);

    float acc[30];
#pragma unroll
    for (int k = 0; k < 30; k++) acc[k] = 0.f;

    for (int dd = tid; dd < 1024; dd += 256) {
        float v = (x[dd] - mean)*inv*g[dd] + bb[dd];
        const float* cwr = cw + dd*30;
#pragma unroll
        for (int k = 0; k < 30; k++)
            acc[k] = fmaf(v, cwr[k], acc[k]);
    }

    __shared__ float sacc[30];
    if (tid < 30) sacc[tid] = 0.f;
    __syncthreads();
#pragma unroll
    for (int k = 0; k < 30; k++) {
        float v = acc[k];
#pragma unroll
        for (int o = 16; o > 0; o >>= 1)
            v += __shfl_down_sync(0xffffffffu, v, o);
        if ((tid & 31) == 0) atomicAdd(&sacc[k], v);
    }
    __syncthreads();
    if (tid < 30)
        out[((size_t)b*1024 + t)*30 + tid] = sacc[tid];
}

// ============================================================
// host orchestration
// ============================================================
extern "C" void kernel_launch(void* const* d_in, const int* in_sizes, int n_in,
                              void* d_out, int out_size) {
    const float* x       = (const float*)d_in[0];
    const float* conv0_w = (const float*)d_in[1];
    const float* conv0_b = (const float*)d_in[2];
    const float* rc1w = (const float*)d_in[3];
    const float* rc1b = (const float*)d_in[4];
    const float* rb1g = (const float*)d_in[5];
    const float* rb1b = (const float*)d_in[6];
    const float* rb1m = (const float*)d_in[7];
    const float* rb1v = (const float*)d_in[8];
    const float* rc2w = (const float*)d_in[9];
    const float* rc2b = (const float*)d_in[10];
    const float* rb2g = (const float*)d_in[11];
    const float* rb2b = (const float*)d_in[12];
    const float* rb2m = (const float*)d_in[13];
    const float* rb2v = (const float*)d_in[14];
    const float* ln0g = (const float*)d_in[15];
    const float* ln0b = (const float*)d_in[16];
    const float* wproj0 = (const float*)d_in[17];
    const float* w0   = (const float*)d_in[18];
    const float* vc0  = (const float*)d_in[19];
    const float* bias0= (const float*)d_in[20];
    const float* lng  = (const float*)d_in[21];
    const float* lnb  = (const float*)d_in[22];
    const float* wproj= (const float*)d_in[23];
    const float* w    = (const float*)d_in[24];
    const float* vc   = (const float*)d_in[25];
    const float* bias = (const float*)d_in[26];
    const float* clng = (const float*)d_in[27];
    const float* clnb = (const float*)d_in[28];
    const float* clsw = (const float*)d_in[29];

    float *bufA, *bufB, *xn, *tmp, *U, *sa, *sb, *wT, *bias2;
    cudaGetSymbolAddress((void**)&bufA,  g_bufA);
    cudaGetSymbolAddress((void**)&bufB,  g_bufB);
    cudaGetSymbolAddress((void**)&xn,    g_xn);
    cudaGetSymbolAddress((void**)&tmp,   g_tmp);
    cudaGetSymbolAddress((void**)&U,     g_U);
    cudaGetSymbolAddress((void**)&sa,    g_sa);
    cudaGetSymbolAddress((void**)&sb,    g_sb);
    cudaGetSymbolAddress((void**)&wT,    g_wT);
    cudaGetSymbolAddress((void**)&bias2, g_bias2);

    dim3 cgrid(4, 64, 16);

    // conv front-end
    conv0_kernel<<<cgrid, 256>>>(x, conv0_w, conv0_b, bufA);

    for (int i = 0; i < 3; i++) {
        prep_conv_kernel<<<9, 1024>>>(rc1w + i*9216, rc1b + i*32,
                                      rb1g + i*32, rb1b + i*32,
                                      rb1m + i*32, rb1v + i*32, wT, bias2);
        resconv_kernel<<<cgrid, 256>>>(bufA, wT, bias2, nullptr, bufB);
        prep_conv_kernel<<<9, 1024>>>(rc2w + i*9216, rc2b + i*32,
                                      rb2g + i*32, rb2b + i*32,
                                      rb2m + i*32, rb2v + i*32, wT, bias2);
        resconv_kernel<<<cgrid, 256>>>(bufB, wT, bias2, bufA, bufA);
    }

    // (b, c*64+f, t) -> (t, b, cf)
    transpose_kernel<<<dim3(32, 64, 16), dim3(32, 8)>>>(bufA, bufB);

    // SRU layer 0 (k=4, feat 2048)
    ln_kernel<<<NROWS, 256>>>(bufB, ln0g, ln0b, xn, 2048);
    sgemm_kernel<<<dim3(256/64, NROWS/128), 256>>>(xn, wproj0, tmp, NROWS, 256, 2048);
    sgemm_kernel<<<dim3(4096/64, NROWS/128), 256>>>(tmp, w0, U, NROWS, 4096, 256);
    sru_kernel<4><<<128, 128>>>(U, xn, vc0, bias0, sa);

    // SRU layers 1-3 (k=3, feat 1024)
    float* cur = sa;
    float* nxt = sb;
    for (int i = 0; i < 3; i++) {
        ln_kernel<<<NROWS, 256>>>(cur, lng + i*1024, lnb + i*1024, xn, 1024);
        sgemm_kernel<<<dim3(256/64, NROWS/128), 256>>>(xn, wproj + (size_t)i*1024*256,
                                                       tmp, NROWS, 256, 1024);
        sgemm_kernel<<<dim3(3072/64, NROWS/128), 256>>>(tmp, w + (size_t)i*256*3072,
                                                        U, NROWS, 3072, 256);
        sru_kernel<3><<<128, 128>>>(U, xn, vc + i*2048, bias + i*2048, nxt);
        float* t2 = cur; cur = nxt; nxt = t2;
    }

    // final LN + classifier
    final_kernel<<<NROWS, 256>>>(cur, clng, clnb, clsw, (float*)d_out);
}

// round 2
// speedup vs baseline: 1.1893x; 1.1893x over previous
#include <cuda_runtime.h>
#include <math.h>
#include <stdint.h>

#define EPSV 1e-5f

// ---- dims ----
#define BB   16
#define CC   32
#define FF   64
#define TT   1024
#define LL   1024
#define HH   512
#define PP   256
#define FEAT2 2048
#define DD   1024
#define NROWS (LL*BB)   // 16384

// ---- scratch (device globals; allocation-free) ----
__device__ float g_bufA[BB*CC*FF*TT];      // 33.55M
__device__ float g_bufB[BB*CC*FF*TT];      // 33.55M
__device__ float g_xn[NROWS*FEAT2];        // 33.55M
__device__ float g_tmp[NROWS*PP];          // 4.19M
__device__ float g_U[NROWS*4096];          // 67.1M
__device__ float g_sa[NROWS*DD];           // 16.78M
__device__ float g_sb[NROWS*DD];           // 16.78M
__device__ float g_wT[CC*CC*9];            // folded+transposed conv weights
__device__ float g_bias2[CC];

// ============================================================
// conv0: x(16,1,128,2048) -> out(16,32,64,1024), 3x3 s2 p1, +bias
// ============================================================
__global__ void conv0_kernel(const float* __restrict__ x,
                             const float* __restrict__ w,
                             const float* __restrict__ cb,
                             float* __restrict__ out) {
    __shared__ float ws[288];   // [j][co]
    __shared__ float bs[32];
    int tid = threadIdx.x;
    for (int i = tid; i < 288; i += 256) {
        int co = i / 9, j = i % 9;
        ws[j*32 + co] = w[i];
    }
    if (tid < 32) bs[tid] = cb[tid];
    __syncthreads();

    int to = blockIdx.x * 256 + tid;   // 0..1023
    int fo = blockIdx.y;               // 0..63
    int b  = blockIdx.z;               // 0..15

    float acc[32];
#pragma unroll
    for (int q = 0; q < 32; q++) acc[q] = bs[q];

#pragma unroll
    for (int df = 0; df < 3; df++) {
        int xi = 2*fo + df - 1;
        if (xi < 0 || xi >= 128) continue;
#pragma unroll
        for (int dt = 0; dt < 3; dt++) {
            int ti = 2*to + dt - 1;
            if (ti < 0 || ti >= 2048) continue;
            float v = x[((size_t)b*128 + xi)*2048 + ti];
            int j = df*3 + dt;
#pragma unroll
            for (int q = 0; q < 8; q++) {
                float4 w4 = *(const float4*)&ws[j*32 + q*4];
                acc[q*4+0] = fmaf(v, w4.x, acc[q*4+0]);
                acc[q*4+1] = fmaf(v, w4.y, acc[q*4+1]);
                acc[q*4+2] = fmaf(v, w4.z, acc[q*4+2]);
                acc[q*4+3] = fmaf(v, w4.w, acc[q*4+3]);
            }
        }
    }
    size_t ob = ((size_t)b*32)*65536 + (size_t)fo*1024 + to;
#pragma unroll
    for (int co = 0; co < 32; co++)
        out[ob + (size_t)co*65536] = acc[co];
}

// ============================================================
// prep: fold BN into conv weights, transpose to [(ci*9+j)][co]
// ============================================================
__global__ void prep_conv_kernel(const float* __restrict__ w,
                                 const float* __restrict__ cb,
                                 const float* __restrict__ g,
                                 const float* __restrict__ beta,
                                 const float* __restrict__ m,
                                 const float* __restrict__ v,
                                 float* __restrict__ wT,
                                 float* __restrict__ bias2) {
    int tid = blockIdx.x * blockDim.x + threadIdx.x;
    if (tid < 9216) {
        int co = tid / 288;
        int r  = tid % 288;                 // ci*9 + j
        float scale = g[co] * rsqrtf(v[co] + EPSV);
        wT[r*32 + co] = w[tid] * scale;
    }
    if (tid < 32) {
        float scale = g[tid] * rsqrtf(v[tid] + EPSV);
        bias2[tid] = beta[tid] + (cb[tid] - m[tid]) * scale;
    }
}

// ============================================================
// residual conv: out = relu( conv3x3(in)*bn + bias2 [+ res] )
// ============================================================
__global__ void resconv_kernel(const float* __restrict__ in,
                               const float* __restrict__ wT,
                               const float* __restrict__ bias2,
                               const float* __restrict__ res,
                               float* __restrict__ out) {
    __shared__ float ws[9216];
    __shared__ float bs[32];
    int tid = threadIdx.x;
    for (int i = tid; i < 2304; i += 256)
        ((float4*)ws)[i] = ((const float4*)wT)[i];
    if (tid < 32) bs[tid] = bias2[tid];
    __syncthreads();

    int t = blockIdx.x * 256 + tid;
    int f = blockIdx.y;
    int b = blockIdx.z;

    float acc[32];
#pragma unroll
    for (int q = 0; q < 32; q++) acc[q] = bs[q];

    bool fm = f > 0, fp = f < 63, tm = t > 0, tp = t < 1023;

    for (int ci = 0; ci < 32; ci++) {
        size_t base = (((size_t)b*32 + ci)*64 + f)*1024 + t;
        float xv[9];
        xv[0] = (fm && tm) ? in[base - 1024 - 1] : 0.f;
        xv[1] =  fm        ? in[base - 1024]     : 0.f;
        xv[2] = (fm && tp) ? in[base - 1024 + 1] : 0.f;
        xv[3] =  tm        ? in[base - 1]        : 0.f;
        xv[4] =              in[base];
        xv[5] =  tp        ? in[base + 1]        : 0.f;
        xv[6] = (fp && tm) ? in[base + 1024 - 1] : 0.f;
        xv[7] =  fp        ? in[base + 1024]     : 0.f;
        xv[8] = (fp && tp) ? in[base + 1024 + 1] : 0.f;

        const float* wr = ws + ci*288;
#pragma unroll
        for (int j = 0; j < 9; j++) {
            float v = xv[j];
#pragma unroll
            for (int q = 0; q < 8; q++) {
                float4 w4 = *(const float4*)&wr[j*32 + q*4];
                acc[q*4+0] = fmaf(v, w4.x, acc[q*4+0]);
                acc[q*4+1] = fmaf(v, w4.y, acc[q*4+1]);
                acc[q*4+2] = fmaf(v, w4.z, acc[q*4+2]);
                acc[q*4+3] = fmaf(v, w4.w, acc[q*4+3]);
            }
        }
    }

    size_t ob = (((size_t)b*32)*64 + f)*1024 + t;
    bool hasres = (res != nullptr);
#pragma unroll
    for (int co = 0; co < 32; co++) {
        float vv = acc[co];
        if (hasres) vv += res[ob + (size_t)co*65536];
        out[ob + (size_t)co*65536] = fmaxf(vv, 0.f);
    }
}

// ============================================================
// transpose: (b, cf=2048, t=1024) -> s[t][b][cf]
// ============================================================
__global__ void transpose_kernel(const float* __restrict__ in,
                                 float* __restrict__ out) {
    __shared__ float tile[32][33];
    int b  = blockIdx.z;
    int t0 = blockIdx.x * 32;
    int c0 = blockIdx.y * 32;
    int tx = threadIdx.x, ty = threadIdx.y;  // (32,8)
#pragma unroll
    for (int i = 0; i < 4; i++)
        tile[ty + 8*i][tx] = in[((size_t)b*2048 + c0 + ty + 8*i)*1024 + t0 + tx];
    __syncthreads();
#pragma unroll
    for (int i = 0; i < 4; i++)
        out[(((size_t)(t0 + ty + 8*i))*16 + b)*2048 + c0 + tx] = tile[tx][ty + 8*i];
}

// ============================================================
// LayerNorm per row (W = 2048 or 1024), 256 threads/row
// ============================================================
__global__ void ln_kernel(const float* __restrict__ in,
                          const float* __restrict__ g,
                          const float* __restrict__ bb,
                          float* __restrict__ out, int W) {
    int row = blockIdx.x;
    int tid = threadIdx.x;
    const float* x = in + (size_t)row * W;

    float s = 0.f, s2 = 0.f;
    for (int i = tid*4; i < W; i += 1024) {
        float4 v = *(const float4*)(x + i);
        s  += v.x + v.y + v.z + v.w;
        s2 += v.x*v.x + v.y*v.y + v.z*v.z + v.w*v.w;
    }
    __shared__ float rs[256], rs2[256];
    rs[tid] = s; rs2[tid] = s2;
    __syncthreads();
    for (int o = 128; o > 0; o >>= 1) {
        if (tid < o) { rs[tid] += rs[tid+o]; rs2[tid] += rs2[tid+o]; }
        __syncthreads();
    }
    float mean = rs[0] / W;
    float var  = rs2[0] / W - mean * mean;
    float inv  = rsqrtf(var + EPSV);

    float* o = out + (size_t)row * W;
    for (int i = tid*4; i < W; i += 1024) {
        float4 v  = *(const float4*)(x + i);
        float4 gg = *(const float4*)(g + i);
        float4 bv = *(const float4*)(bb + i);
        float4 r;
        r.x = (v.x - mean)*inv*gg.x + bv.x;
        r.y = (v.y - mean)*inv*gg.y + bv.y;
        r.z = (v.z - mean)*inv*gg.z + bv.z;
        r.w = (v.w - mean)*inv*gg.w + bv.w;
        *(float4*)(o + i) = r;
    }
}

// ============================================================
// TF32 tensor-core GEMM: C[M,N] = A[M,K] @ B[K,N], fp32 in/out
// BM=128, BN=128, BK=32; 256 threads (8 warps, 4x2), warp tile 32x64
// mma.sync.m16n8k8.tf32, cvt.rna at staging, reg-prefetch pipeline
// M%128==0, N%128==0, K%32==0 guaranteed
// ============================================================
__device__ __forceinline__ uint32_t f2tf(float x) {
    uint32_t u;
    asm("cvt.rna.tf32.f32 %0, %1;" : "=r"(u) : "f"(x));
    return u;
}

__device__ __forceinline__ void mma_tf32(float* c, const uint32_t* a, const uint32_t* b) {
    asm volatile(
        "mma.sync.aligned.m16n8k8.row.col.f32.tf32.tf32.f32 "
        "{%0,%1,%2,%3}, {%4,%5,%6,%7}, {%8,%9}, {%0,%1,%2,%3};\n"
        : "+f"(c[0]), "+f"(c[1]), "+f"(c[2]), "+f"(c[3])
        : "r"(a[0]), "r"(a[1]), "r"(a[2]), "r"(a[3]),
          "r"(b[0]), "r"(b[1]));
}

__global__ __launch_bounds__(256)
void mma_gemm_kernel(const float* __restrict__ A,
                     const float* __restrict__ Bm,
                     float* __restrict__ Cm,
                     int M, int N, int K) {
    // [k][m] / [k][n], stride 136 words -> bank = 8*(k&3) + m  (conflict-free)
    __shared__ uint32_t As[32][136];
    __shared__ uint32_t Bs[32][136];

    int tid  = threadIdx.x;
    int lane = tid & 31, warp = tid >> 5;
    int m0 = blockIdx.y * 128, n0 = blockIdx.x * 128;
    int wm = (warp >> 1) * 32;   // 4 warps along m
    int wn = (warp & 1) * 64;    // 2 warps along n
    int g  = lane >> 2, tg = lane & 3;

    float acc[2][8][4];
#pragma unroll
    for (int mt = 0; mt < 2; mt++)
#pragma unroll
        for (int nt = 0; nt < 8; nt++)
#pragma unroll
            for (int i = 0; i < 4; i++) acc[mt][nt][i] = 0.f;

    // staging assignment
    int ac = tid & 3;          // A col low bits (0..3)
    int ar = tid >> 2;         // A row (0..63), also +64
    int bk = tid >> 5;         // B k row (0..7), +8l
    int bc = (tid & 31) * 4;   // B col (0..124)

    const float* aptr0 = A + (size_t)(m0 + ar) * K + ac;
    const float* aptr1 = A + (size_t)(m0 + ar + 64) * K + ac;
    const float* bptr  = Bm + (size_t)bk * N + n0 + bc;

    float  areg[16];
    float4 breg[4];

    // prologue: load k0 = 0
#pragma unroll
    for (int p = 0; p < 8; p++) {
        areg[p]     = aptr0[4*p];
        areg[8 + p] = aptr1[4*p];
    }
#pragma unroll
    for (int l = 0; l < 4; l++)
        breg[l] = *(const float4*)(bptr + (size_t)(8*l) * N);

    for (int k0 = 0; k0 < K; k0 += 32) {
        // stage regs -> SMEM (cvt to tf32)
#pragma unroll
        for (int p = 0; p < 8; p++) {
            As[ac + 4*p][ar]      = f2tf(areg[p]);
            As[ac + 4*p][ar + 64] = f2tf(areg[8 + p]);
        }
#pragma unroll
        for (int l = 0; l < 4; l++) {
            uint4 u;
            u.x = f2tf(breg[l].x); u.y = f2tf(breg[l].y);
            u.z = f2tf(breg[l].z); u.w = f2tf(breg[l].w);
            *(uint4*)&Bs[bk + 8*l][bc] = u;
        }
        __syncthreads();

        // prefetch next tile while tensor pipe works
        if (k0 + 32 < K) {
            int kn = k0 + 32;
#pragma unroll
            for (int p = 0; p < 8; p++) {
                areg[p]     = aptr0[kn + 4*p];
                areg[8 + p] = aptr1[kn + 4*p];
            }
#pragma unroll
            for (int l = 0; l < 4; l++)
                breg[l] = *(const float4*)(bptr + (size_t)(kn + 8*l) * N);
        }

        // compute
#pragma unroll
        for (int kc = 0; kc < 4; kc++) {
            int kb = kc * 8;
            uint32_t af[2][4];
#pragma unroll
            for (int mt = 0; mt < 2; mt++) {
                int row = wm + mt*16 + g;
                af[mt][0] = As[kb + tg][row];
                af[mt][1] = As[kb + tg][row + 8];
                af[mt][2] = As[kb + 4 + tg][row];
                af[mt][3] = As[kb + 4 + tg][row + 8];
            }
            uint32_t bf[8][2];
#pragma unroll
            for (int nt = 0; nt < 8; nt++) {
                int col = wn + nt*8 + g;
                bf[nt][0] = Bs[kb + tg][col];
                bf[nt][1] = Bs[kb + 4 + tg][col];
            }
#pragma unroll
            for (int mt = 0; mt < 2; mt++)
#pragma unroll
                for (int nt = 0; nt < 8; nt++)
                    mma_tf32(acc[mt][nt], af[mt], bf[nt]);
        }
        __syncthreads();
    }

    // epilogue
#pragma unroll
    for (int mt = 0; mt < 2; mt++) {
        int row = m0 + wm + mt*16 + g;
#pragma unroll
        for (int nt = 0; nt < 8; nt++) {
            int col = n0 + wn + nt*8 + tg*2;
            float2 v0 = make_float2(acc[mt][nt][0], acc[mt][nt][1]);
            float2 v1 = make_float2(acc[mt][nt][2], acc[mt][nt][3]);
            *(float2*)&Cm[(size_t)row * N + col]       = v0;
            *(float2*)&Cm[(size_t)(row + 8) * N + col] = v1;
        }
    }
}

// ============================================================
// SRU recurrence
// ============================================================
__device__ __forceinline__ float sigmf(float x) {
    return 1.f / (1.f + __expf(-x));
}

template <int KK>
__global__ void sru_kernel(const float* __restrict__ U,
                           const float* __restrict__ xn,
                           const float* __restrict__ vc,
                           const float* __restrict__ bias,
                           float* __restrict__ out) {
    int idx = blockIdx.x * blockDim.x + threadIdx.x;  // 0..16383
    int j = idx & 511;
    int b = (idx >> 9) & 15;
    int d = idx >> 13;

    float vf = vc[d*1024 + j],       vr = vc[d*1024 + 512 + j];
    float bf = bias[d*1024 + j],     br = bias[d*1024 + 512 + j];

    const int RW = 2*KK*512;
    int colbase = b*RW + d*KK*512 + j;
    int obase   = b*1024 + d*512 + j;

    float c = 0.f;
#pragma unroll 2
    for (int s = 0; s < 1024; s++) {
        int t = d ? (1023 - s) : s;
        size_t off = (size_t)t*16*RW + colbase;
        float a0 = U[off];
        float a1 = U[off + 512];
        float a2 = U[off + 1024];
        float rx = (KK == 4) ? U[off + 1536]
                             : xn[(size_t)t*16*1024 + obase];
        float f = sigmf(fmaf(vf, c, a1) + bf);
        c = fmaf(f, c - a0, a0);
        float r = sigmf(fmaf(vr, c, a2) + br);
        out[(size_t)t*16*1024 + obase] = fmaf(r, c - rx, rx);
    }
}

// ============================================================
// final: per row (t*16+b): LN over 1024 then @ cls_w(1024,30)
// ============================================================
__global__ void final_kernel(const float* __restrict__ s,
                             const float* __restrict__ g,
                             const float* __restrict__ bb,
                             const float* __restrict__ cw,
                             float* __restrict__ out) {
    int row = blockIdx.x;       // t*16 + b
    int t = row >> 4, b = row & 15;
    int tid = threadIdx.x;      // 256
    const float* x = s + (size_t)row * 1024;

    float4 v4 = *(const float4*)(x + tid*4);
    float sm = v4.x + v4.y + v4.z + v4.w;
    float s2 = v4.x*v4.x + v4.y*v4.y + v4.z*v4.z + v4.w*v4.w;

    __shared__ float rs[256], rs2[256];
    rs[tid] = sm; rs2[tid] = s2;
    __syncthreads();
    for (int o = 128; o > 0; o >>= 1) {
        if (tid < o) { rs[tid] += rs[tid+o]; rs2[tid] += rs2[tid+o]; }
        __syncthreads();
    }
    float mean = rs[0] * (1.f/1024.f);
    float var  = rs2[0] * (1.f/1024.f) - mean*mean;
    float inv  = rsqrtf(var + EPSV);

    float acc[30];
#pragma unroll
    for (int k = 0; k < 30; k++) acc[k] = 0.f;

    for (int dd = tid; dd < 1024; dd += 256) {
        float v = (x[dd] - mean)*inv*g[dd] + bb[dd];
        const float* cwr = cw + dd*30;
#pragma unroll
        for (int k = 0; k < 30; k++)
            acc[k] = fmaf(v, cwr[k], acc[k]);
    }

    __shared__ float sacc[30];
    if (tid < 30) sacc[tid] = 0.f;
    __syncthreads();
#pragma unroll
    for (int k = 0; k < 30; k++) {
        float v = acc[k];
#pragma unroll
        for (int o = 16; o > 0; o >>= 1)
            v += __shfl_down_sync(0xffffffffu, v, o);
        if ((tid & 31) == 0) atomicAdd(&sacc[k], v);
    }
    __syncthreads();
    if (tid < 30)
        out[((size_t)b*1024 + t)*30 + tid] = sacc[tid];
}

// ============================================================
// host orchestration
// ============================================================
extern "C" void kernel_launch(void* const* d_in, const int* in_sizes, int n_in,
                              void* d_out, int out_size) {
    const float* x       = (const float*)d_in[0];
    const float* conv0_w = (const float*)d_in[1];
    const float* conv0_b = (const float*)d_in[2];
    const float* rc1w = (const float*)d_in[3];
    const float* rc1b = (const float*)d_in[4];
    const float* rb1g = (const float*)d_in[5];
    const float* rb1b = (const float*)d_in[6];
    const float* rb1m = (const float*)d_in[7];
    const float* rb1v = (const float*)d_in[8];
    const float* rc2w = (const float*)d_in[9];
    const float* rc2b = (const float*)d_in[10];
    const float* rb2g = (const float*)d_in[11];
    const float* rb2b = (const float*)d_in[12];
    const float* rb2m = (const float*)d_in[13];
    const float* rb2v = (const float*)d_in[14];
    const float* ln0g = (const float*)d_in[15];
    const float* ln0b = (const float*)d_in[16];
    const float* wproj0 = (const float*)d_in[17];
    const float* w0   = (const float*)d_in[18];
    const float* vc0  = (const float*)d_in[19];
    const float* bias0= (const float*)d_in[20];
    const float* lng  = (const float*)d_in[21];
    const float* lnb  = (const float*)d_in[22];
    const float* wproj= (const float*)d_in[23];
    const float* w    = (const float*)d_in[24];
    const float* vc   = (const float*)d_in[25];
    const float* bias = (const float*)d_in[26];
    const float* clng = (const float*)d_in[27];
    const float* clnb = (const float*)d_in[28];
    const float* clsw = (const float*)d_in[29];

    float *bufA, *bufB, *xn, *tmp, *U, *sa, *sb, *wT, *bias2;
    cudaGetSymbolAddress((void**)&bufA,  g_bufA);
    cudaGetSymbolAddress((void**)&bufB,  g_bufB);
    cudaGetSymbolAddress((void**)&xn,    g_xn);
    cudaGetSymbolAddress((void**)&tmp,   g_tmp);
    cudaGetSymbolAddress((void**)&U,     g_U);
    cudaGetSymbolAddress((void**)&sa,    g_sa);
    cudaGetSymbolAddress((void**)&sb,    g_sb);
    cudaGetSymbolAddress((void**)&wT,    g_wT);
    cudaGetSymbolAddress((void**)&bias2, g_bias2);

    dim3 cgrid(4, 64, 16);

    // conv front-end
    conv0_kernel<<<cgrid, 256>>>(x, conv0_w, conv0_b, bufA);

    for (int i = 0; i < 3; i++) {
        prep_conv_kernel<<<9, 1024>>>(rc1w + i*9216, rc1b + i*32,
                                      rb1g + i*32, rb1b + i*32,
                                      rb1m + i*32, rb1v + i*32, wT, bias2);
        resconv_kernel<<<cgrid, 256>>>(bufA, wT, bias2, nullptr, bufB);
        prep_conv_kernel<<<9, 1024>>>(rc2w + i*9216, rc2b + i*32,
                                      rb2g + i*32, rb2b + i*32,
                                      rb2m + i*32, rb2v + i*32, wT, bias2);
        resconv_kernel<<<cgrid, 256>>>(bufB, wT, bias2, bufA, bufA);
    }

    // (b, c*64+f, t) -> (t, b, cf)
    transpose_kernel<<<dim3(32, 64, 16), dim3(32, 8)>>>(bufA, bufB);

    // SRU layer 0 (k=4, feat 2048)
    ln_kernel<<<NROWS, 256>>>(bufB, ln0g, ln0b, xn, 2048);
    mma_gemm_kernel<<<dim3(256/128, NROWS/128), 256>>>(xn, wproj0, tmp, NROWS, 256, 2048);
    mma_gemm_kernel<<<dim3(4096/128, NROWS/128), 256>>>(tmp, w0, U, NROWS, 4096, 256);
    sru_kernel<4><<<128, 128>>>(U, xn, vc0, bias0, sa);

    // SRU layers 1-3 (k=3, feat 1024)
    float* cur = sa;
    float* nxt = sb;
    for (int i = 0; i < 3; i++) {
        ln_kernel<<<NROWS, 256>>>(cur, lng + i*1024, lnb + i*1024, xn, 1024);
        mma_gemm_kernel<<<dim3(256/128, NROWS/128), 256>>>(xn, wproj + (size_t)i*1024*256,
                                                           tmp, NROWS, 256, 1024);
        mma_gemm_kernel<<<dim3(3072/128, NROWS/128), 256>>>(tmp, w + (size_t)i*256*3072,
                                                            U, NROWS, 3072, 256);
        sru_kernel<3><<<128, 128>>>(U, xn, vc + i*2048, bias + i*2048, nxt);
        float* t2 = cur; cur = nxt; nxt = t2;
    }

    // final LN + classifier
    final_kernel<<<NROWS, 256>>>(cur, clng, clnb, clsw, (float*)d_out);
}

// round 3
// speedup vs baseline: 1.4198x; 1.1939x over previous
#include <cuda_runtime.h>
#include <cuda_fp16.h>
#include <math.h>
#include <stdint.h>

#define EPSV 1e-5f

// ---- dims ----
#define BB   16
#define CC   32
#define FF   64
#define TT   1024
#define LL   1024
#define HH   512
#define PP   256
#define FEAT2 2048
#define DD   1024
#define NROWS (LL*BB)   // 16384

// ---- scratch (device globals; allocation-free) ----
__device__ float g_bufA[BB*CC*FF*TT];      // NHWC [b][f][t][c]
__device__ float g_bufB[BB*CC*FF*TT];
__device__ float g_xn[NROWS*FEAT2];
__device__ float g_tmp[NROWS*PP];
__device__ float g_U[NROWS*4096];
__device__ float g_sa[NROWS*DD];
__device__ float g_sb[NROWS*DD];
__device__ uint32_t g_w1[144*40];          // fp16 hi weights, [kk][co] pad40
__device__ uint32_t g_w2[144*40];          // fp16 lo weights
__device__ float g_bias2[CC];

// ============================================================
// conv0: x(16,1,128,2048) -> NHWC out[b][f][t][c], 3x3 s2 p1
// ============================================================
__global__ void conv0_kernel(const float* __restrict__ x,
                             const float* __restrict__ w,
                             const float* __restrict__ cb,
                             float* __restrict__ out) {
    __shared__ float ws[288];   // [j][co]
    __shared__ float bs[32];
    int tid = threadIdx.x;
    for (int i = tid; i < 288; i += 256) {
        int co = i / 9, j = i % 9;
        ws[j*32 + co] = w[i];
    }
    if (tid < 32) bs[tid] = cb[tid];
    __syncthreads();

    int to = blockIdx.x * 256 + tid;   // 0..1023
    int fo = blockIdx.y;               // 0..63
    int b  = blockIdx.z;               // 0..15

    float acc[32];
#pragma unroll
    for (int q = 0; q < 32; q++) acc[q] = bs[q];

#pragma unroll
    for (int df = 0; df < 3; df++) {
        int xi = 2*fo + df - 1;
        if (xi < 0 || xi >= 128) continue;
#pragma unroll
        for (int dt = 0; dt < 3; dt++) {
            int ti = 2*to + dt - 1;
            if (ti < 0 || ti >= 2048) continue;
            float v = x[((size_t)b*128 + xi)*2048 + ti];
            int j = df*3 + dt;
#pragma unroll
            for (int q = 0; q < 8; q++) {
                float4 w4 = *(const float4*)&ws[j*32 + q*4];
                acc[q*4+0] = fmaf(v, w4.x, acc[q*4+0]);
                acc[q*4+1] = fmaf(v, w4.y, acc[q*4+1]);
                acc[q*4+2] = fmaf(v, w4.z, acc[q*4+2]);
                acc[q*4+3] = fmaf(v, w4.w, acc[q*4+3]);
            }
        }
    }
    // NHWC write: 32 contiguous channels
    size_t ob = (((size_t)b*64 + fo)*1024 + to)*32;
#pragma unroll
    for (int q = 0; q < 8; q++)
        *(float4*)&out[ob + q*4] = make_float4(acc[q*4], acc[q*4+1], acc[q*4+2], acc[q*4+3]);
}

// ============================================================
// prep: fold BN into conv weights, split fp16 hi/lo, pack pairs
// along k (k = j*32+ci, kk = j*16+ci/2), layout [kk][co] pad 40
// ============================================================
__global__ void prep_conv_kernel(const float* __restrict__ w,
                                 const float* __restrict__ cb,
                                 const float* __restrict__ g,
                                 const float* __restrict__ beta,
                                 const float* __restrict__ m,
                                 const float* __restrict__ v,
                                 uint32_t* __restrict__ w1,
                                 uint32_t* __restrict__ w2,
                                 float* __restrict__ bias2) {
    int i = blockIdx.x * blockDim.x + threadIdx.x;
    if (i < 4608) {
        int co  = i & 31;
        int kk  = i >> 5;              // 0..143
        int j   = kk >> 4;
        int ci2 = kk & 15;
        float scale = g[co] * rsqrtf(v[co] + EPSV);
        float f0 = w[co*288 + (2*ci2    )*9 + j] * scale;
        float f1 = w[co*288 + (2*ci2 + 1)*9 + j] * scale;
        __half h0 = __float2half_rn(f0), h1 = __float2half_rn(f1);
        __half l0 = __float2half_rn(f0 - __half2float(h0));
        __half l1 = __float2half_rn(f1 - __half2float(h1));
        __half2 hi = __halves2half2(h0, h1);
        __half2 lo = __halves2half2(l0, l1);
        w1[kk*40 + co] = *(uint32_t*)&hi;
        w2[kk*40 + co] = *(uint32_t*)&lo;
    }
    if (i < 32) {
        float scale = g[i] * rsqrtf(v[i] + EPSV);
        bias2[i] = beta[i] + (cb[i] - m[i]) * scale;
    }
}

// ============================================================
// residual conv via fp16x3 tensor-core implicit GEMM
// block: (t0=bx*128, f=by, b=bz); 256 thr; out NHWC
// K=288 fully SMEM-resident. acc = a1*b1 + a2*b1 + a1*b2 (fp32 acc)
// ============================================================
__device__ __forceinline__ void mma_f16(float* c, const uint32_t* a, const uint32_t* b) {
    asm volatile(
        "mma.sync.aligned.m16n8k16.row.col.f32.f16.f16.f32 "
        "{%0,%1,%2,%3}, {%4,%5,%6,%7}, {%8,%9}, {%0,%1,%2,%3};\n"
        : "+f"(c[0]), "+f"(c[1]), "+f"(c[2]), "+f"(c[3])
        : "r"(a[0]), "r"(a[1]), "r"(a[2]), "r"(a[3]),
          "r"(b[0]), "r"(b[1]));
}

// SMEM word offsets
#define RC_A1 0            // [3][130][20]
#define RC_A2 7800
#define RC_W1 15600        // [144][40]
#define RC_W2 21360
#define RC_WORDS 27120     // * 4 = 108480 bytes

__global__ __launch_bounds__(256)
void resconv_mma_kernel(const float* __restrict__ in,
                        const uint32_t* __restrict__ w1g,
                        const uint32_t* __restrict__ w2g,
                        const float* __restrict__ bias2,
                        const float* __restrict__ res,
                        float* __restrict__ out) {
    extern __shared__ uint32_t sm[];
    uint32_t* A1 = sm + RC_A1;
    uint32_t* A2 = sm + RC_A2;
    uint32_t* W1 = sm + RC_W1;
    uint32_t* W2 = sm + RC_W2;
    __shared__ float bs[32];

    int tid = threadIdx.x;
    int t0 = blockIdx.x * 128;
    int f  = blockIdx.y;
    int b  = blockIdx.z;

    if (tid < 32) bs[tid] = bias2[tid];

    // stage weights (5760 words each = 1440 uint4)
    for (int i = tid; i < 1440; i += 256) {
        ((uint4*)W1)[i] = ((const uint4*)w1g)[i];
        ((uint4*)W2)[i] = ((const uint4*)w2g)[i];
    }

    // stage 3 input slabs [130 rows][32 ch], split hi/lo, pack k-pairs
#pragma unroll
    for (int df = 0; df < 3; df++) {
        int xi = f + df - 1;
        bool xok = (xi >= 0) && (xi < 64);
        const float* src = in + (((size_t)b*64 + xi)*1024 + (t0 - 1))*32;
        uint32_t* d1 = A1 + df*2600;
        uint32_t* d2 = A2 + df*2600;
        for (int idx = tid*4; idx < 130*32; idx += 1024) {
            int r = idx >> 5;
            int t = t0 - 1 + r;
            float4 v = make_float4(0.f, 0.f, 0.f, 0.f);
            if (xok && t >= 0 && t < 1024)
                v = *(const float4*)(src + idx);
            __half hx = __float2half_rn(v.x), hy = __float2half_rn(v.y);
            __half hz = __float2half_rn(v.z), hw = __float2half_rn(v.w);
            __half lx = __float2half_rn(v.x - __half2float(hx));
            __half ly = __float2half_rn(v.y - __half2float(hy));
            __half lz = __float2half_rn(v.z - __half2float(hz));
            __half lw = __float2half_rn(v.w - __half2float(hw));
            __half2 h01 = __halves2half2(hx, hy), h23 = __halves2half2(hz, hw);
            __half2 l01 = __halves2half2(lx, ly), l23 = __halves2half2(lz, lw);
            int base = r*20 + ((idx & 31) >> 1);
            uint2 u1 = make_uint2(*(uint32_t*)&h01, *(uint32_t*)&h23);
            uint2 u2 = make_uint2(*(uint32_t*)&l01, *(uint32_t*)&l23);
            *(uint2*)&d1[base] = u1;
            *(uint2*)&d2[base] = u2;
        }
    }
    __syncthreads();

    int lane = tid & 31, warp = tid >> 5;
    int g = lane >> 2, tg = lane & 3;
    int rowA = warp * 16;

    float acc[4][4];
#pragma unroll
    for (int nt = 0; nt < 4; nt++)
#pragma unroll
        for (int i = 0; i < 4; i++) acc[nt][i] = 0.f;

#pragma unroll
    for (int j = 0; j < 9; j++) {
        const int df = j / 3, dt = j % 3;
        const uint32_t* a1s = A1 + df*2600 + (rowA + dt)*20;
        const uint32_t* a2s = A2 + df*2600 + (rowA + dt)*20;
        const uint32_t* w1s = W1 + (j*16)*40;
        const uint32_t* w2s = W2 + (j*16)*40;
#pragma unroll
        for (int h = 0; h < 2; h++) {
            int kb = h*8;
            uint32_t a1f[4], a2f[4];
            a1f[0] = a1s[(g    )*20 + kb + tg];
            a1f[1] = a1s[(g + 8)*20 + kb + tg];
            a1f[2] = a1s[(g    )*20 + kb + tg + 4];
            a1f[3] = a1s[(g + 8)*20 + kb + tg + 4];
            a2f[0] = a2s[(g    )*20 + kb + tg];
            a2f[1] = a2s[(g + 8)*20 + kb + tg];
            a2f[2] = a2s[(g    )*20 + kb + tg + 4];
            a2f[3] = a2s[(g + 8)*20 + kb + tg + 4];
#pragma unroll
            for (int nt = 0; nt < 4; nt++) {
                uint32_t b1f[2], b2f[2];
                b1f[0] = w1s[(kb + tg    )*40 + nt*8 + g];
                b1f[1] = w1s[(kb + tg + 4)*40 + nt*8 + g];
                b2f[0] = w2s[(kb + tg    )*40 + nt*8 + g];
                b2f[1] = w2s[(kb + tg + 4)*40 + nt*8 + g];
                mma_f16(acc[nt], a1f, b1f);
                mma_f16(acc[nt], a2f, b1f);
                mma_f16(acc[nt], a1f, b2f);
            }
        }
    }

    // epilogue: +bias (+res) relu, NHWC
    bool hasres = (res != nullptr);
#pragma unroll
    for (int nt = 0; nt < 4; nt++) {
        int co = nt*8 + tg*2;
#pragma unroll
        for (int half = 0; half < 2; half++) {
            int t = t0 + rowA + g + half*8;
            size_t addr = (((size_t)b*64 + f)*1024 + t)*32 + co;
            float v0 = acc[nt][half*2 + 0] + bs[co];
            float v1 = acc[nt][half*2 + 1] + bs[co + 1];
            if (hasres) {
                float2 rv = *(const float2*)(res + addr);
                v0 += rv.x; v1 += rv.y;
            }
            float2 o = make_float2(fmaxf(v0, 0.f), fmaxf(v1, 0.f));
            *(float2*)(out + addr) = o;
        }
    }
}

// ============================================================
// transpose: NHWC [b][f][t][c] -> s[(t*16+b)][c*64+f]
// ============================================================
__global__ void transpose_nhwc_kernel(const float* __restrict__ in,
                                      float* __restrict__ out) {
    __shared__ float tile[64][33];
    int t = blockIdx.x, b = blockIdx.y;
    int tid = threadIdx.x;  // 256
    for (int i = tid; i < 512; i += 256) {
        int fq = i >> 3, c4 = (i & 7)*4;
        float4 v = *(const float4*)(in + (((size_t)b*64 + fq)*1024 + t)*32 + c4);
        tile[fq][c4]   = v.x; tile[fq][c4+1] = v.y;
        tile[fq][c4+2] = v.z; tile[fq][c4+3] = v.w;
    }
    __syncthreads();
    size_t ob = ((size_t)t*16 + b)*2048;
    for (int i = tid; i < 2048; i += 256) {
        int c = i >> 6, ff = i & 63;
        out[ob + i] = tile[ff][c];
    }
}

// ============================================================
// LayerNorm per row (W = 2048 or 1024), 256 threads/row
// ============================================================
__global__ void ln_kernel(const float* __restrict__ in,
                          const float* __restrict__ g,
                          const float* __restrict__ bb,
                          float* __restrict__ out, int W) {
    int row = blockIdx.x;
    int tid = threadIdx.x;
    const float* x = in + (size_t)row * W;

    float s = 0.f, s2 = 0.f;
    for (int i = tid*4; i < W; i += 1024) {
        float4 v = *(const float4*)(x + i);
        s  += v.x + v.y + v.z + v.w;
        s2 += v.x*v.x + v.y*v.y + v.z*v.z + v.w*v.w;
    }
    __shared__ float rs[256], rs2[256];
    rs[tid] = s; rs2[tid] = s2;
    __syncthreads();
    for (int o = 128; o > 0; o >>= 1) {
        if (tid < o) { rs[tid] += rs[tid+o]; rs2[tid] += rs2[tid+o]; }
        __syncthreads();
    }
    float mean = rs[0] / W;
    float var  = rs2[0] / W - mean * mean;
    float inv  = rsqrtf(var + EPSV);

    float* o = out + (size_t)row * W;
    for (int i = tid*4; i < W; i += 1024) {
        float4 v  = *(const float4*)(x + i);
        float4 gg = *(const float4*)(g + i);
        float4 bv = *(const float4*)(bb + i);
        float4 r;
        r.x = (v.x - mean)*inv*gg.x + bv.x;
        r.y = (v.y - mean)*inv*gg.y + bv.y;
        r.z = (v.z - mean)*inv*gg.z + bv.z;
        r.w = (v.w - mean)*inv*gg.w + bv.w;
        *(float4*)(o + i) = r;
    }
}

// ============================================================
// TF32 tensor-core GEMM (unchanged from R2)
// ============================================================
__device__ __forceinline__ uint32_t f2tf(float x) {
    uint32_t u;
    asm("cvt.rna.tf32.f32 %0, %1;" : "=r"(u) : "f"(x));
    return u;
}

__device__ __forceinline__ void mma_tf32(float* c, const uint32_t* a, const uint32_t* b) {
    asm volatile(
        "mma.sync.aligned.m16n8k8.row.col.f32.tf32.tf32.f32 "
        "{%0,%1,%2,%3}, {%4,%5,%6,%7}, {%8,%9}, {%0,%1,%2,%3};\n"
        : "+f"(c[0]), "+f"(c[1]), "+f"(c[2]), "+f"(c[3])
        : "r"(a[0]), "r"(a[1]), "r"(a[2]), "r"(a[3]),
          "r"(b[0]), "r"(b[1]));
}

__global__ __launch_bounds__(256)
void mma_gemm_kernel(const float* __restrict__ A,
                     const float* __restrict__ Bm,
                     float* __restrict__ Cm,
                     int M, int N, int K) {
    __shared__ uint32_t As[32][136];
    __shared__ uint32_t Bs[32][136];

    int tid  = threadIdx.x;
    int lane = tid & 31, warp = tid >> 5;
    int m0 = blockIdx.y * 128, n0 = blockIdx.x * 128;
    int wm = (warp >> 1) * 32;
    int wn = (warp & 1) * 64;
    int g  = lane >> 2, tg = lane & 3;

    float acc[2][8][4];
#pragma unroll
    for (int mt = 0; mt < 2; mt++)
#pragma unroll
        for (int nt = 0; nt < 8; nt++)
#pragma unroll
            for (int i = 0; i < 4; i++) acc[mt][nt][i] = 0.f;

    int ac = tid & 3;
    int ar = tid >> 2;
    int bk = tid >> 5;
    int bc = (tid & 31) * 4;

    const float* aptr0 = A + (size_t)(m0 + ar) * K + ac;
    const float* aptr1 = A + (size_t)(m0 + ar + 64) * K + ac;
    const float* bptr  = Bm + (size_t)bk * N + n0 + bc;

    float  areg[16];
    float4 breg[4];

#pragma unroll
    for (int p = 0; p < 8; p++) {
        areg[p]     = aptr0[4*p];
        areg[8 + p] = aptr1[4*p];
    }
#pragma unroll
    for (int l = 0; l < 4; l++)
        breg[l] = *(const float4*)(bptr + (size_t)(8*l) * N);

    for (int k0 = 0; k0 < K; k0 += 32) {
#pragma unroll
        for (int p = 0; p < 8; p++) {
            As[ac + 4*p][ar]      = f2tf(areg[p]);
            As[ac + 4*p][ar + 64] = f2tf(areg[8 + p]);
        }
#pragma unroll
        for (int l = 0; l < 4; l++) {
            uint4 u;
            u.x = f2tf(breg[l].x); u.y = f2tf(breg[l].y);
            u.z = f2tf(breg[l].z); u.w = f2tf(breg[l].w);
            *(uint4*)&Bs[bk + 8*l][bc] = u;
        }
        __syncthreads();

        if (k0 + 32 < K) {
            int kn = k0 + 32;
#pragma unroll
            for (int p = 0; p < 8; p++) {
                areg[p]     = aptr0[kn + 4*p];
                areg[8 + p] = aptr1[kn + 4*p];
            }
#pragma unroll
            for (int l = 0; l < 4; l++)
                breg[l] = *(const float4*)(bptr + (size_t)(kn + 8*l) * N);
        }

#pragma unroll
        for (int kc = 0; kc < 4; kc++) {
            int kb = kc * 8;
            uint32_t af[2][4];
#pragma unroll
            for (int mt = 0; mt < 2; mt++) {
                int row = wm + mt*16 + g;
                af[mt][0] = As[kb + tg][row];
                af[mt][1] = As[kb + tg][row + 8];
                af[mt][2] = As[kb + 4 + tg][row];
                af[mt][3] = As[kb + 4 + tg][row + 8];
            }
            uint32_t bf[8][2];
#pragma unroll
            for (int nt = 0; nt < 8; nt++) {
                int col = wn + nt*8 + g;
                bf[nt][0] = Bs[kb + tg][col];
                bf[nt][1] = Bs[kb + 4 + tg][col];
            }
#pragma unroll
            for (int mt = 0; mt < 2; mt++)
#pragma unroll
                for (int nt = 0; nt < 8; nt++)
                    mma_tf32(acc[mt][nt], af[mt], bf[nt]);
        }
        __syncthreads();
    }

#pragma unroll
    for (int mt = 0; mt < 2; mt++) {
        int row = m0 + wm + mt*16 + g;
#pragma unroll
        for (int nt = 0; nt < 8; nt++) {
            int col = n0 + wn + nt*8 + tg*2;
            float2 v0 = make_float2(acc[mt][nt][0], acc[mt][nt][1]);
            float2 v1 = make_float2(acc[mt][nt][2], acc[mt][nt][3]);
            *(float2*)&Cm[(size_t)row * N + col]       = v0;
            *(float2*)&Cm[(size_t)(row + 8) * N + col] = v1;
        }
    }
}

// ============================================================
// SRU recurrence
// ============================================================
__device__ __forceinline__ float sigmf(float x) {
    return 1.f / (1.f + __expf(-x));
}

template <int KK>
__global__ void sru_kernel(const float* __restrict__ U,
                           const float* __restrict__ xn,
                           const float* __restrict__ vc,
                           const float* __restrict__ bias,
                           float* __restrict__ out) {
    int idx = blockIdx.x * blockDim.x + threadIdx.x;
    int j = idx & 511;
    int b = (idx >> 9) & 15;
    int d = idx >> 13;

    float vf = vc[d*1024 + j],       vr = vc[d*1024 + 512 + j];
    float bf = bias[d*1024 + j],     br = bias[d*1024 + 512 + j];

    const int RW = 2*KK*512;
    int colbase = b*RW + d*KK*512 + j;
    int obase   = b*1024 + d*512 + j;

    float c = 0.f;
#pragma unroll 2
    for (int s = 0; s < 1024; s++) {
        int t = d ? (1023 - s) : s;
        size_t off = (size_t)t*16*RW + colbase;
        float a0 = U[off];
        float a1 = U[off + 512];
        float a2 = U[off + 1024];
        float rx = (KK == 4) ? U[off + 1536]
                             : xn[(size_t)t*16*1024 + obase];
        float f = sigmf(fmaf(vf, c, a1) + bf);
        c = fmaf(f, c - a0, a0);
        float r = sigmf(fmaf(vr, c, a2) + br);
        out[(size_t)t*16*1024 + obase] = fmaf(r, c - rx, rx);
    }
}

// ============================================================
// final: per row (t*16+b): LN over 1024 then @ cls_w(1024,30)
// ============================================================
__global__ void final_kernel(const float* __restrict__ s,
                             const float* __restrict__ g,
                             const float* __restrict__ bb,
                             const float* __restrict__ cw,
                             float* __restrict__ out) {
    int row = blockIdx.x;
    int t = row >> 4, b = row & 15;
    int tid = threadIdx.x;
    const float* x = s + (size_t)row * 1024;

    float4 v4 = *(const float4*)(x + tid*4);
    float sm = v4.x + v4.y + v4.z + v4.w;
    float s2 = v4.x*v4.x + v4.y*v4.y + v4.z*v4.z + v4.w*v4.w;

    __shared__ float rs[256], rs2[256];
    rs[tid] = sm; rs2[tid] = s2;
    __syncthreads();
    for (int o = 128; o > 0; o >>= 1) {
        if (tid < o) { rs[tid] += rs[tid+o]; rs2[tid] += rs2[tid+o]; }
        __syncthreads();
    }
    float mean = rs[0] * (1.f/1024.f);
    float var  = rs2[0] * (1.f/1024.f) - mean*mean;
    float inv  = rsqrtf(var + EPSV);

    float acc[30];
#pragma unroll
    for (int k = 0; k < 30; k++) acc[k] = 0.f;

    for (int dd = tid; dd < 1024; dd += 256) {
        float v = (x[dd] - mean)*inv*g[dd] + bb[dd];
        const float* cwr = cw + dd*30;
#pragma unroll
        for (int k = 0; k < 30; k++)
            acc[k] = fmaf(v, cwr[k], acc[k]);
    }

    __shared__ float sacc[30];
    if (tid < 30) sacc[tid] = 0.f;
    __syncthreads();
#pragma unroll
    for (int k = 0; k < 30; k++) {
        float v = acc[k];
#pragma unroll
        for (int o = 16; o > 0; o >>= 1)
            v += __shfl_down_sync(0xffffffffu, v, o);
        if ((tid & 31) == 0) atomicAdd(&sacc[k], v);
    }
    __syncthreads();
    if (tid < 30)
        out[((size_t)b*1024 + t)*30 + tid] = sacc[tid];
}

// ============================================================
// host orchestration
// ============================================================
extern "C" void kernel_launch(void* const* d_in, const int* in_sizes, int n_in,
                              void* d_out, int out_size) {
    const float* x       = (const float*)d_in[0];
    const float* conv0_w = (const float*)d_in[1];
    const float* conv0_b = (const float*)d_in[2];
    const float* rc1w = (const float*)d_in[3];
    const float* rc1b = (const float*)d_in[4];
    const float* rb1g = (const float*)d_in[5];
    const float* rb1b = (const float*)d_in[6];
    const float* rb1m = (const float*)d_in[7];
    const float* rb1v = (const float*)d_in[8];
    const float* rc2w = (const float*)d_in[9];
    const float* rc2b = (const float*)d_in[10];
    const float* rb2g = (const float*)d_in[11];
    const float* rb2b = (const float*)d_in[12];
    const float* rb2m = (const float*)d_in[13];
    const float* rb2v = (const float*)d_in[14];
    const float* ln0g = (const float*)d_in[15];
    const float* ln0b = (const float*)d_in[16];
    const float* wproj0 = (const float*)d_in[17];
    const float* w0   = (const float*)d_in[18];
    const float* vc0  = (const float*)d_in[19];
    const float* bias0= (const float*)d_in[20];
    const float* lng  = (const float*)d_in[21];
    const float* lnb  = (const float*)d_in[22];
    const float* wproj= (const float*)d_in[23];
    const float* w    = (const float*)d_in[24];
    const float* vc   = (const float*)d_in[25];
    const float* bias = (const float*)d_in[26];
    const float* clng = (const float*)d_in[27];
    const float* clnb = (const float*)d_in[28];
    const float* clsw = (const float*)d_in[29];

    float *bufA, *bufB, *xn, *tmp, *U, *sa, *sb, *bias2;
    uint32_t *w1, *w2;
    cudaGetSymbolAddress((void**)&bufA,  g_bufA);
    cudaGetSymbolAddress((void**)&bufB,  g_bufB);
    cudaGetSymbolAddress((void**)&xn,    g_xn);
    cudaGetSymbolAddress((void**)&tmp,   g_tmp);
    cudaGetSymbolAddress((void**)&U,     g_U);
    cudaGetSymbolAddress((void**)&sa,    g_sa);
    cudaGetSymbolAddress((void**)&sb,    g_sb);
    cudaGetSymbolAddress((void**)&w1,    g_w1);
    cudaGetSymbolAddress((void**)&w2,    g_w2);
    cudaGetSymbolAddress((void**)&bias2, g_bias2);

    cudaFuncSetAttribute(resconv_mma_kernel,
                         cudaFuncAttributeMaxDynamicSharedMemorySize, RC_WORDS*4);

    // conv front-end (NHWC)
    conv0_kernel<<<dim3(4, 64, 16), 256>>>(x, conv0_w, conv0_b, bufA);

    dim3 rcgrid(8, 64, 16);
    for (int i = 0; i < 3; i++) {
        prep_conv_kernel<<<5, 1024>>>(rc1w + i*9216, rc1b + i*32,
                                      rb1g + i*32, rb1b + i*32,
                                      rb1m + i*32, rb1v + i*32, w1, w2, bias2);
        resconv_mma_kernel<<<rcgrid, 256, RC_WORDS*4>>>(bufA, w1, w2, bias2, nullptr, bufB);
        prep_conv_kernel<<<5, 1024>>>(rc2w + i*9216, rc2b + i*32,
                                      rb2g + i*32, rb2b + i*32,
                                      rb2m + i*32, rb2v + i*32, w1, w2, bias2);
        resconv_mma_kernel<<<rcgrid, 256, RC_WORDS*4>>>(bufB, w1, w2, bias2, bufA, bufA);
    }

    // NHWC -> s[t*16+b][c*64+f]
    transpose_nhwc_kernel<<<dim3(1024, 16), 256>>>(bufA, bufB);

    // SRU layer 0 (k=4, feat 2048)
    ln_kernel<<<NROWS, 256>>>(bufB, ln0g, ln0b, xn, 2048);
    mma_gemm_kernel<<<dim3(256/128, NROWS/128), 256>>>(xn, wproj0, tmp, NROWS, 256, 2048);
    mma_gemm_kernel<<<dim3(4096/128, NROWS/128), 256>>>(tmp, w0, U, NROWS, 4096, 256);
    sru_kernel<4><<<128, 128>>>(U, xn, vc0, bias0, sa);

    // SRU layers 1-3 (k=3, feat 1024)
    float* cur = sa;
    float* nxt = sb;
    for (int i = 0; i < 3; i++) {
        ln_kernel<<<NROWS, 256>>>(cur, lng + i*1024, lnb + i*1024, xn, 1024);
        mma_gemm_kernel<<<dim3(256/128, NROWS/128), 256>>>(xn, wproj + (size_t)i*1024*256,
                                                           tmp, NROWS, 256, 1024);
        mma_gemm_kernel<<<dim3(3072/128, NROWS/128), 256>>>(tmp, w + (size_t)i*256*3072,
                                                            U, NROWS, 3072, 256);
        sru_kernel<3><<<128, 128>>>(U, xn, vc + i*2048, bias + i*2048, nxt);
        float* t2 = cur; cur = nxt; nxt = t2;
    }

    // final LN + classifier
    final_kernel<<<NROWS, 256>>>(cur, clng, clnb, clsw, (float*)d_out);
}

// round 5
// speedup vs baseline: 2.1339x; 1.5029x over previous
#include <cuda_runtime.h>
#include <cuda_fp16.h>
#include <math.h>
#include <stdint.h>

#define EPSV 1e-5f

// ---- dims ----
#define BB   16
#define CC   32
#define FF   64
#define TT   1024
#define LL   1024
#define HH   512
#define PP   256
#define FEAT2 2048
#define DD   1024
#define NROWS (LL*BB)   // 16384

// single dynamic-SMEM symbol shared by all kernels
extern __shared__ char dynsmem[];

// ---- scratch (device globals; allocation-free) ----
__device__ float g_bufA[BB*CC*FF*TT];      // NHWC [b][f][t][c]
__device__ float g_bufB[BB*CC*FF*TT];
__device__ float g_xn[NROWS*FEAT2];
__device__ float g_tmp[NROWS*PP];
__device__ float g_U[NROWS*4096];
__device__ float g_sa[NROWS*DD];
__device__ float g_sb[NROWS*DD];
__device__ uint32_t g_w1[144*40];          // fp16 hi weights, [kk][co] pad40
__device__ uint32_t g_w2[144*40];          // fp16 lo weights
__device__ float g_bias2[CC];

__device__ __forceinline__ void cpa16(void* smem, const void* gmem) {
    uint32_t s = (uint32_t)__cvta_generic_to_shared(smem);
    asm volatile("cp.async.cg.shared.global [%0], [%1], 16;\n" :: "r"(s), "l"(gmem));
}

// ============================================================
// conv0: x(16,1,128,2048) -> NHWC out[b][f][t][c], 3x3 s2 p1
// ============================================================
__global__ void conv0_kernel(const float* __restrict__ x,
                             const float* __restrict__ w,
                             const float* __restrict__ cb,
                             float* __restrict__ out) {
    __shared__ float ws[288];   // [j][co]
    __shared__ float bs[32];
    int tid = threadIdx.x;
    for (int i = tid; i < 288; i += 256) {
        int co = i / 9, j = i % 9;
        ws[j*32 + co] = w[i];
    }
    if (tid < 32) bs[tid] = cb[tid];
    __syncthreads();

    int to = blockIdx.x * 256 + tid;   // 0..1023
    int fo = blockIdx.y;               // 0..63
    int b  = blockIdx.z;               // 0..15

    float acc[32];
#pragma unroll
    for (int q = 0; q < 32; q++) acc[q] = bs[q];

#pragma unroll
    for (int df = 0; df < 3; df++) {
        int xi = 2*fo + df - 1;
        if (xi < 0 || xi >= 128) continue;
#pragma unroll
        for (int dt = 0; dt < 3; dt++) {
            int ti = 2*to + dt - 1;
            if (ti < 0 || ti >= 2048) continue;
            float v = x[((size_t)b*128 + xi)*2048 + ti];
            int j = df*3 + dt;
#pragma unroll
            for (int q = 0; q < 8; q++) {
                float4 w4 = *(const float4*)&ws[j*32 + q*4];
                acc[q*4+0] = fmaf(v, w4.x, acc[q*4+0]);
                acc[q*4+1] = fmaf(v, w4.y, acc[q*4+1]);
                acc[q*4+2] = fmaf(v, w4.z, acc[q*4+2]);
                acc[q*4+3] = fmaf(v, w4.w, acc[q*4+3]);
            }
        }
    }
    size_t ob = (((size_t)b*64 + fo)*1024 + to)*32;
#pragma unroll
    for (int q = 0; q < 8; q++)
        *(float4*)&out[ob + q*4] = make_float4(acc[q*4], acc[q*4+1], acc[q*4+2], acc[q*4+3]);
}

// ============================================================
// prep: fold BN into conv weights, split fp16 hi/lo
// ============================================================
__global__ void prep_conv_kernel(const float* __restrict__ w,
                                 const float* __restrict__ cb,
                                 const float* __restrict__ g,
                                 const float* __restrict__ beta,
                                 const float* __restrict__ m,
                                 const float* __restrict__ v,
                                 uint32_t* __restrict__ w1,
                                 uint32_t* __restrict__ w2,
                                 float* __restrict__ bias2) {
    int i = blockIdx.x * blockDim.x + threadIdx.x;
    if (i < 4608) {
        int co  = i & 31;
        int kk  = i >> 5;              // 0..143
        int j   = kk >> 4;
        int ci2 = kk & 15;
        float scale = g[co] * rsqrtf(v[co] + EPSV);
        float f0 = w[co*288 + (2*ci2    )*9 + j] * scale;
        float f1 = w[co*288 + (2*ci2 + 1)*9 + j] * scale;
        __half h0 = __float2half_rn(f0), h1 = __float2half_rn(f1);
        __half l0 = __float2half_rn(f0 - __half2float(h0));
        __half l1 = __float2half_rn(f1 - __half2float(h1));
        __half2 hi = __halves2half2(h0, h1);
        __half2 lo = __halves2half2(l0, l1);
        w1[kk*40 + co] = *(uint32_t*)&hi;
        w2[kk*40 + co] = *(uint32_t*)&lo;
    }
    if (i < 32) {
        float scale = g[i] * rsqrtf(v[i] + EPSV);
        bias2[i] = beta[i] + (cb[i] - m[i]) * scale;
    }
}

// ============================================================
// residual conv via fp16x3 tensor-core implicit GEMM
// ============================================================
__device__ __forceinline__ void mma_f16(float* c, const uint32_t* a, const uint32_t* b) {
    asm volatile(
        "mma.sync.aligned.m16n8k16.row.col.f32.f16.f16.f32 "
        "{%0,%1,%2,%3}, {%4,%5,%6,%7}, {%8,%9}, {%0,%1,%2,%3};\n"
        : "+f"(c[0]), "+f"(c[1]), "+f"(c[2]), "+f"(c[3])
        : "r"(a[0]), "r"(a[1]), "r"(a[2]), "r"(a[3]),
          "r"(b[0]), "r"(b[1]));
}

#define RC_A1 0            // [3][130][20]
#define RC_A2 7800
#define RC_W1 15600        // [144][40]
#define RC_W2 21360
#define RC_WORDS 27120

__global__ __launch_bounds__(256)
void resconv_mma_kernel(const float* __restrict__ in,
                        const uint32_t* __restrict__ w1g,
                        const uint32_t* __restrict__ w2g,
                        const float* __restrict__ bias2,
                        const float* __restrict__ res,
                        float* __restrict__ out) {
    uint32_t* sm = (uint32_t*)dynsmem;
    uint32_t* A1 = sm + RC_A1;
    uint32_t* A2 = sm + RC_A2;
    uint32_t* W1 = sm + RC_W1;
    uint32_t* W2 = sm + RC_W2;
    __shared__ float bs[32];

    int tid = threadIdx.x;
    int t0 = blockIdx.x * 128;
    int f  = blockIdx.y;
    int b  = blockIdx.z;

    if (tid < 32) bs[tid] = bias2[tid];

    for (int i = tid; i < 1440; i += 256) {
        ((uint4*)W1)[i] = ((const uint4*)w1g)[i];
        ((uint4*)W2)[i] = ((const uint4*)w2g)[i];
    }

#pragma unroll
    for (int df = 0; df < 3; df++) {
        int xi = f + df - 1;
        bool xok = (xi >= 0) && (xi < 64);
        const float* src = in + (((size_t)b*64 + xi)*1024 + (t0 - 1))*32;
        uint32_t* d1 = A1 + df*2600;
        uint32_t* d2 = A2 + df*2600;
        for (int idx = tid*4; idx < 130*32; idx += 1024) {
            int r = idx >> 5;
            int t = t0 - 1 + r;
            float4 v = make_float4(0.f, 0.f, 0.f, 0.f);
            if (xok && t >= 0 && t < 1024)
                v = *(const float4*)(src + idx);
            __half hx = __float2half_rn(v.x), hy = __float2half_rn(v.y);
            __half hz = __float2half_rn(v.z), hw = __float2half_rn(v.w);
            __half lx = __float2half_rn(v.x - __half2float(hx));
            __half ly = __float2half_rn(v.y - __half2float(hy));
            __half lz = __float2half_rn(v.z - __half2float(hz));
            __half lw = __float2half_rn(v.w - __half2float(hw));
            __half2 h01 = __halves2half2(hx, hy), h23 = __halves2half2(hz, hw);
            __half2 l01 = __halves2half2(lx, ly), l23 = __halves2half2(lz, lw);
            int base = r*20 + ((idx & 31) >> 1);
            *(uint2*)&d1[base] = make_uint2(*(uint32_t*)&h01, *(uint32_t*)&h23);
            *(uint2*)&d2[base] = make_uint2(*(uint32_t*)&l01, *(uint32_t*)&l23);
        }
    }
    __syncthreads();

    int lane = tid & 31, warp = tid >> 5;
    int g = lane >> 2, tg = lane & 3;
    int rowA = warp * 16;

    float acc[4][4];
#pragma unroll
    for (int nt = 0; nt < 4; nt++)
#pragma unroll
        for (int i = 0; i < 4; i++) acc[nt][i] = 0.f;

#pragma unroll
    for (int j = 0; j < 9; j++) {
        const int df = j / 3, dt = j % 3;
        const uint32_t* a1s = A1 + df*2600 + (rowA + dt)*20;
        const uint32_t* a2s = A2 + df*2600 + (rowA + dt)*20;
        const uint32_t* w1s = W1 + (j*16)*40;
        const uint32_t* w2s = W2 + (j*16)*40;
#pragma unroll
        for (int h = 0; h < 2; h++) {
            int kb = h*8;
            uint32_t a1f[4], a2f[4];
            a1f[0] = a1s[(g    )*20 + kb + tg];
            a1f[1] = a1s[(g + 8)*20 + kb + tg];
            a1f[2] = a1s[(g    )*20 + kb + tg + 4];
            a1f[3] = a1s[(g + 8)*20 + kb + tg + 4];
            a2f[0] = a2s[(g    )*20 + kb + tg];
            a2f[1] = a2s[(g + 8)*20 + kb + tg];
            a2f[2] = a2s[(g    )*20 + kb + tg + 4];
            a2f[3] = a2s[(g + 8)*20 + kb + tg + 4];
#pragma unroll
            for (int nt = 0; nt < 4; nt++) {
                uint32_t b1f[2], b2f[2];
                b1f[0] = w1s[(kb + tg    )*40 + nt*8 + g];
                b1f[1] = w1s[(kb + tg + 4)*40 + nt*8 + g];
                b2f[0] = w2s[(kb + tg    )*40 + nt*8 + g];
                b2f[1] = w2s[(kb + tg + 4)*40 + nt*8 + g];
                mma_f16(acc[nt], a1f, b1f);
                mma_f16(acc[nt], a2f, b1f);
                mma_f16(acc[nt], a1f, b2f);
            }
        }
    }

    bool hasres = (res != nullptr);
#pragma unroll
    for (int nt = 0; nt < 4; nt++) {
        int co = nt*8 + tg*2;
#pragma unroll
        for (int half = 0; half < 2; half++) {
            int t = t0 + rowA + g + half*8;
            size_t addr = (((size_t)b*64 + f)*1024 + t)*32 + co;
            float v0 = acc[nt][half*2 + 0] + bs[co];
            float v1 = acc[nt][half*2 + 1] + bs[co + 1];
            if (hasres) {
                float2 rv = *(const float2*)(res + addr);
                v0 += rv.x; v1 += rv.y;
            }
            *(float2*)(out + addr) = make_float2(fmaxf(v0, 0.f), fmaxf(v1, 0.f));
        }
    }
}

// ============================================================
// fused transpose + LayerNorm(2048):
// NHWC [b][f][t][c] -> xn[(t*16+b)][c*64+f] normalized
// ============================================================
__global__ void transpose_ln_kernel(const float* __restrict__ in,
                                    const float* __restrict__ g,
                                    const float* __restrict__ bb,
                                    float* __restrict__ out) {
    __shared__ float tile[64][33];
    __shared__ float rs[256], rs2[256];
    int t = blockIdx.x, b = blockIdx.y;
    int tid = threadIdx.x;  // 256
    float s = 0.f, s2 = 0.f;
    for (int i = tid; i < 512; i += 256) {
        int fq = i >> 3, c4 = (i & 7)*4;
        float4 v = *(const float4*)(in + (((size_t)b*64 + fq)*1024 + t)*32 + c4);
        tile[fq][c4]   = v.x; tile[fq][c4+1] = v.y;
        tile[fq][c4+2] = v.z; tile[fq][c4+3] = v.w;
        s  += v.x + v.y + v.z + v.w;
        s2 += v.x*v.x + v.y*v.y + v.z*v.z + v.w*v.w;
    }
    rs[tid] = s; rs2[tid] = s2;
    __syncthreads();
    for (int o = 128; o > 0; o >>= 1) {
        if (tid < o) { rs[tid] += rs[tid+o]; rs2[tid] += rs2[tid+o]; }
        __syncthreads();
    }
    float mean = rs[0] * (1.f/2048.f);
    float var  = rs2[0] * (1.f/2048.f) - mean*mean;
    float inv  = rsqrtf(var + EPSV);

    size_t ob = ((size_t)t*16 + b)*2048;
    for (int i = tid; i < 2048; i += 256) {
        int c = i >> 6, ff = i & 63;
        out[ob + i] = (tile[ff][c] - mean)*inv*g[i] + bb[i];
    }
}

// ============================================================
// LayerNorm per row (W=1024), 256 threads/row
// ============================================================
__global__ void ln_kernel(const float* __restrict__ in,
                          const float* __restrict__ g,
                          const float* __restrict__ bb,
                          float* __restrict__ out, int W) {
    int row = blockIdx.x;
    int tid = threadIdx.x;
    const float* x = in + (size_t)row * W;

    float s = 0.f, s2 = 0.f;
    for (int i = tid*4; i < W; i += 1024) {
        float4 v = *(const float4*)(x + i);
        s  += v.x + v.y + v.z + v.w;
        s2 += v.x*v.x + v.y*v.y + v.z*v.z + v.w*v.w;
    }
    __shared__ float rs[256], rs2[256];
    rs[tid] = s; rs2[tid] = s2;
    __syncthreads();
    for (int o = 128; o > 0; o >>= 1) {
        if (tid < o) { rs[tid] += rs[tid+o]; rs2[tid] += rs2[tid+o]; }
        __syncthreads();
    }
    float mean = rs[0] / W;
    float var  = rs2[0] / W - mean * mean;
    float inv  = rsqrtf(var + EPSV);

    float* o = out + (size_t)row * W;
    for (int i = tid*4; i < W; i += 1024) {
        float4 v  = *(const float4*)(x + i);
        float4 gg = *(const float4*)(g + i);
        float4 bv = *(const float4*)(bb + i);
        float4 r;
        r.x = (v.x - mean)*inv*gg.x + bv.x;
        r.y = (v.y - mean)*inv*gg.y + bv.y;
        r.z = (v.z - mean)*inv*gg.z + bv.z;
        r.w = (v.w - mean)*inv*gg.w + bv.w;
        *(float4*)(o + i) = r;
    }
}

// ============================================================
// TF32 GEMM v2: double-buffered SMEM, one sync per k-iter
// BM=128,BN=128,BK=32; 256 thr; warp tile 32x64
// ============================================================
__device__ __forceinline__ uint32_t f2tf(float x) {
    uint32_t u;
    asm("cvt.rna.tf32.f32 %0, %1;" : "=r"(u) : "f"(x));
    return u;
}

__device__ __forceinline__ void mma_tf32(float* c, const uint32_t* a, const uint32_t* b) {
    asm volatile(
        "mma.sync.aligned.m16n8k8.row.col.f32.tf32.tf32.f32 "
        "{%0,%1,%2,%3}, {%4,%5,%6,%7}, {%8,%9}, {%0,%1,%2,%3};\n"
        : "+f"(c[0]), "+f"(c[1]), "+f"(c[2]), "+f"(c[3])
        : "r"(a[0]), "r"(a[1]), "r"(a[2]), "r"(a[3]),
          "r"(b[0]), "r"(b[1]));
}

#define GTW (32*136)   // words per A (or B) tile

__global__ __launch_bounds__(256)
void mma_gemm_kernel(const float* __restrict__ A,
                     const float* __restrict__ Bm,
                     float* __restrict__ Cm,
                     int M, int N, int K) {
    uint32_t* gsm = (uint32_t*)dynsmem;   // [2][A 32x136 | B 32x136]

    int tid  = threadIdx.x;
    int lane = tid & 31, warp = tid >> 5;
    int m0 = blockIdx.y * 128, n0 = blockIdx.x * 128;
    int wm = (warp >> 1) * 32;
    int wn = (warp & 1) * 64;
    int g  = lane >> 2, tg = lane & 3;

    float acc[2][8][4];
#pragma unroll
    for (int mt = 0; mt < 2; mt++)
#pragma unroll
        for (int nt = 0; nt < 8; nt++)
#pragma unroll
            for (int i = 0; i < 4; i++) acc[mt][nt][i] = 0.f;

    int ac = tid & 3;
    int ar = tid >> 2;
    int bk = tid >> 5;
    int bc = (tid & 31) * 4;

    const float* aptr0 = A + (size_t)(m0 + ar) * K + ac;
    const float* aptr1 = A + (size_t)(m0 + ar + 64) * K + ac;
    const float* bptr  = Bm + (size_t)bk * N + n0 + bc;

    float  areg[16];
    float4 breg[4];

    // prologue: load + stage tile 0
#pragma unroll
    for (int p = 0; p < 8; p++) {
        areg[p]     = aptr0[4*p];
        areg[8 + p] = aptr1[4*p];
    }
#pragma unroll
    for (int l = 0; l < 4; l++)
        breg[l] = *(const float4*)(bptr + (size_t)(8*l) * N);

    {
        uint32_t* asb = gsm;
        uint32_t* bsb = gsm + GTW;
#pragma unroll
        for (int p = 0; p < 8; p++) {
            asb[(ac + 4*p)*136 + ar]      = f2tf(areg[p]);
            asb[(ac + 4*p)*136 + ar + 64] = f2tf(areg[8 + p]);
        }
#pragma unroll
        for (int l = 0; l < 4; l++) {
            uint4 u;
            u.x = f2tf(breg[l].x); u.y = f2tf(breg[l].y);
            u.z = f2tf(breg[l].z); u.w = f2tf(breg[l].w);
            *(uint4*)&bsb[(bk + 8*l)*136 + bc] = u;
        }
    }
    __syncthreads();

    int cur = 0;
    for (int k0 = 0; k0 < K; k0 += 32) {
        bool hn = (k0 + 32) < K;
        if (hn) {
            int kn = k0 + 32;
#pragma unroll
            for (int p = 0; p < 8; p++) {
                areg[p]     = aptr0[kn + 4*p];
                areg[8 + p] = aptr1[kn + 4*p];
            }
#pragma unroll
            for (int l = 0; l < 4; l++)
                breg[l] = *(const float4*)(bptr + (size_t)(kn + 8*l) * N);
        }

        const uint32_t* asc = gsm + cur*2*GTW;
        const uint32_t* bsc = asc + GTW;

#pragma unroll
        for (int kc = 0; kc < 4; kc++) {
            int kb = kc * 8;
            uint32_t af[2][4];
#pragma unroll
            for (int mt = 0; mt < 2; mt++) {
                int row = wm + mt*16 + g;
                af[mt][0] = asc[(kb + tg)*136 + row];
                af[mt][1] = asc[(kb + tg)*136 + row + 8];
                af[mt][2] = asc[(kb + 4 + tg)*136 + row];
                af[mt][3] = asc[(kb + 4 + tg)*136 + row + 8];
            }
            uint32_t bf[8][2];
#pragma unroll
            for (int nt = 0; nt < 8; nt++) {
                int col = wn + nt*8 + g;
                bf[nt][0] = bsc[(kb + tg)*136 + col];
                bf[nt][1] = bsc[(kb + 4 + tg)*136 + col];
            }
#pragma unroll
            for (int mt = 0; mt < 2; mt++)
#pragma unroll
                for (int nt = 0; nt < 8; nt++)
                    mma_tf32(acc[mt][nt], af[mt], bf[nt]);
        }

        if (hn) {
            uint32_t* asb = gsm + (cur^1)*2*GTW;
            uint32_t* bsb = asb + GTW;
#pragma unroll
            for (int p = 0; p < 8; p++) {
                asb[(ac + 4*p)*136 + ar]      = f2tf(areg[p]);
                asb[(ac + 4*p)*136 + ar + 64] = f2tf(areg[8 + p]);
            }
#pragma unroll
            for (int l = 0; l < 4; l++) {
                uint4 u;
                u.x = f2tf(breg[l].x); u.y = f2tf(breg[l].y);
                u.z = f2tf(breg[l].z); u.w = f2tf(breg[l].w);
                *(uint4*)&bsb[(bk + 8*l)*136 + bc] = u;
            }
            __syncthreads();
            cur ^= 1;
        }
    }

#pragma unroll
    for (int mt = 0; mt < 2; mt++) {
        int row = m0 + wm + mt*16 + g;
#pragma unroll
        for (int nt = 0; nt < 8; nt++) {
            int col = n0 + wn + nt*8 + tg*2;
            *(float2*)&Cm[(size_t)row * N + col]       = make_float2(acc[mt][nt][0], acc[mt][nt][1]);
            *(float2*)&Cm[(size_t)(row + 8) * N + col] = make_float2(acc[mt][nt][2], acc[mt][nt][3]);
        }
    }
}

// ============================================================
// SRU v2: block per (d,b), 512 thr (j), cp.async 8-step chunks
// ============================================================
__device__ __forceinline__ float sigmf(float x) {
    return __fdividef(1.f, 1.f + __expf(-x));
}

template <int KK>
__global__ __launch_bounds__(512)
void sru2_kernel(const float* __restrict__ U,
                 const float* __restrict__ xn,
                 const float* __restrict__ vc,
                 const float* __restrict__ bias,
                 float* __restrict__ out) {
    float* sm = (float*)dynsmem;
    const int USTEP = KK*512;
    float* ub = sm;                 // [2][8][USTEP]
    float* xb = sm + 2*8*USTEP;     // [2][8][512] (KK==3)

    const int j = threadIdx.x;
    const int d = blockIdx.x >> 4;
    const int b = blockIdx.x & 15;
    const int RW = 2*KK*512;

    float vf = vc[d*1024 + j],   vr = vc[d*1024 + 512 + j];
    float bf = bias[d*1024 + j], br = bias[d*1024 + 512 + j];

#define SRU_LOAD_CHUNK(cc, buf) do {                                          \
    int s0 = (cc)*8;                                                          \
    for (int idx = j; idx < 8*KK*128; idx += 512) {                           \
        int i = idx / (KK*128);                                               \
        int o = idx - i*(KK*128);                                             \
        int t = d ? (1023 - (s0+i)) : (s0+i);                                 \
        const float* src = U + ((size_t)t*16 + b)*RW + d*USTEP + o*4;         \
        cpa16(ub + ((buf)*8 + i)*USTEP + o*4, src);                           \
    }                                                                         \
    if (KK == 3) {                                                            \
        for (int idx = j; idx < 1024; idx += 512) {                           \
            int i = idx >> 7;                                                 \
            int o = idx & 127;                                                \
            int t = d ? (1023 - (s0+i)) : (s0+i);                             \
            const float* src = xn + ((size_t)t*16 + b)*1024 + d*512 + o*4;    \
            cpa16(xb + ((buf)*8 + i)*512 + o*4, src);                         \
        }                                                                     \
    }                                                                         \
    asm volatile("cp.async.commit_group;\n");                                 \
} while (0)

    SRU_LOAD_CHUNK(0, 0);

    float c = 0.f;
    for (int ch = 0; ch < 128; ch++) {
        int buf = ch & 1;
        if (ch < 127) {
            SRU_LOAD_CHUNK(ch + 1, buf ^ 1);
            asm volatile("cp.async.wait_group 1;\n");
        } else {
            asm volatile("cp.async.wait_group 0;\n");
        }
        __syncthreads();
#pragma unroll
        for (int i = 0; i < 8; i++) {
            int s = ch*8 + i;
            int t = d ? (1023 - s) : s;
            const float* us = ub + (buf*8 + i)*USTEP;
            float a0 = us[j], a1 = us[512 + j], a2 = us[1024 + j];
            float rx = (KK == 4) ? us[1536 + j] : xb[(buf*8 + i)*512 + j];
            float f = sigmf(fmaf(vf, c, a1) + bf);
            c = fmaf(f, c - a0, a0);
            float r = sigmf(fmaf(vr, c, a2) + br);
            out[((size_t)t*16 + b)*1024 + d*512 + j] = fmaf(r, c - rx, rx);
        }
        __syncthreads();
    }
#undef SRU_LOAD_CHUNK
}

// ============================================================
// final: per row LN(1024) + @cls_w(1024,30)
// ============================================================
__global__ void final_kernel(const float* __restrict__ s,
                             const float* __restrict__ g,
                             const float* __restrict__ bb,
                             const float* __restrict__ cw,
                             float* __restrict__ out) {
    int row = blockIdx.x;
    int t = row >> 4, b = row & 15;
    int tid = threadIdx.x;
    const float* x = s + (size_t)row * 1024;

    float4 v4 = *(const float4*)(x + tid*4);
    float sm = v4.x + v4.y + v4.z + v4.w;
    float s2 = v4.x*v4.x + v4.y*v4.y + v4.z*v4.z + v4.w*v4.w;

    __shared__ float rs[256], rs2[256];
    rs[tid] = sm; rs2[tid] = s2;
    __syncthreads();
    for (int o = 128; o > 0; o >>= 1) {
        if (tid < o) { rs[tid] += rs[tid+o]; rs2[tid] += rs2[tid+o]; }
        __syncthreads();
    }
    float mean = rs[0] * (1.f/1024.f);
    float var  = rs2[0] * (1.f/1024.f) - mean*mean;
    float inv  = rsqrtf(var + EPSV);

    float acc[30];
#pragma unroll
    for (int k = 0; k < 30; k++) acc[k] = 0.f;

    for (int dd = tid; dd < 1024; dd += 256) {
        float v = (x[dd] - mean)*inv*g[dd] + bb[dd];
        const float* cwr = cw + dd*30;
#pragma unroll
        for (int k = 0; k < 30; k++)
            acc[k] = fmaf(v, cwr[k], acc[k]);
    }

    __shared__ float sacc[30];
    if (tid < 30) sacc[tid] = 0.f;
    __syncthreads();
#pragma unroll
    for (int k = 0; k < 30; k++) {
        float v = acc[k];
#pragma unroll
        for (int o = 16; o > 0; o >>= 1)
            v += __shfl_down_sync(0xffffffffu, v, o);
        if ((tid & 31) == 0) atomicAdd(&sacc[k], v);
    }
    __syncthreads();
    if (tid < 30)
        out[((size_t)b*1024 + t)*30 + tid] = sacc[tid];
}

// ============================================================
// host orchestration
// ============================================================
extern "C" void kernel_launch(void* const* d_in, const int* in_sizes, int n_in,
                              void* d_out, int out_size) {
    const float* x       = (const float*)d_in[0];
    const float* conv0_w = (const float*)d_in[1];
    const float* conv0_b = (const float*)d_in[2];
    const float* rc1w = (const float*)d_in[3];
    const float* rc1b = (const float*)d_in[4];
    const float* rb1g = (const float*)d_in[5];
    const float* rb1b = (const float*)d_in[6];
    const float* rb1m = (const float*)d_in[7];
    const float* rb1v = (const float*)d_in[8];
    const float* rc2w = (const float*)d_in[9];
    const float* rc2b = (const float*)d_in[10];
    const float* rb2g = (const float*)d_in[11];
    const float* rb2b = (const float*)d_in[12];
    const float* rb2m = (const float*)d_in[13];
    const float* rb2v = (const float*)d_in[14];
    const float* ln0g = (const float*)d_in[15];
    const float* ln0b = (const float*)d_in[16];
    const float* wproj0 = (const float*)d_in[17];
    const float* w0   = (const float*)d_in[18];
    const float* vc0  = (const float*)d_in[19];
    const float* bias0= (const float*)d_in[20];
    const float* lng  = (const float*)d_in[21];
    const float* lnb  = (const float*)d_in[22];
    const float* wproj= (const float*)d_in[23];
    const float* w    = (const float*)d_in[24];
    const float* vc   = (const float*)d_in[25];
    const float* bias = (const float*)d_in[26];
    const float* clng = (const float*)d_in[27];
    const float* clnb = (const float*)d_in[28];
    const float* clsw = (const float*)d_in[29];

    float *bufA, *bufB, *xn, *tmp, *U, *sa, *sb, *bias2;
    uint32_t *w1, *w2;
    cudaGetSymbolAddress((void**)&bufA,  g_bufA);
    cudaGetSymbolAddress((void**)&bufB,  g_bufB);
    cudaGetSymbolAddress((void**)&xn,    g_xn);
    cudaGetSymbolAddress((void**)&tmp,   g_tmp);
    cudaGetSymbolAddress((void**)&U,     g_U);
    cudaGetSymbolAddress((void**)&sa,    g_sa);
    cudaGetSymbolAddress((void**)&sb,    g_sb);
    cudaGetSymbolAddress((void**)&w1,    g_w1);
    cudaGetSymbolAddress((void**)&w2,    g_w2);
    cudaGetSymbolAddress((void**)&bias2, g_bias2);

    cudaFuncSetAttribute(resconv_mma_kernel,
                         cudaFuncAttributeMaxDynamicSharedMemorySize, RC_WORDS*4);
    cudaFuncSetAttribute(mma_gemm_kernel,
                         cudaFuncAttributeMaxDynamicSharedMemorySize, 4*GTW*4);
    cudaFuncSetAttribute(sru2_kernel<4>,
                         cudaFuncAttributeMaxDynamicSharedMemorySize, 131072);
    cudaFuncSetAttribute(sru2_kernel<3>,
                         cudaFuncAttributeMaxDynamicSharedMemorySize, 131072);

    // conv front-end (NHWC)
    conv0_kernel<<<dim3(4, 64, 16), 256>>>(x, conv0_w, conv0_b, bufA);

    dim3 rcgrid(8, 64, 16);
    for (int i = 0; i < 3; i++) {
        prep_conv_kernel<<<5, 1024>>>(rc1w + i*9216, rc1b + i*32,
                                      rb1g + i*32, rb1b + i*32,
                                      rb1m + i*32, rb1v + i*32, w1, w2, bias2);
        resconv_mma_kernel<<<rcgrid, 256, RC_WORDS*4>>>(bufA, w1, w2, bias2, nullptr, bufB);
        prep_conv_kernel<<<5, 1024>>>(rc2w + i*9216, rc2b + i*32,
                                      rb2g + i*32, rb2b + i*32,
                                      rb2m + i*32, rb2v + i*32, w1, w2, bias2);
        resconv_mma_kernel<<<rcgrid, 256, RC_WORDS*4>>>(bufB, w1, w2, bias2, bufA, bufA);
    }

    // fused NHWC->seq transpose + LN(2048) -> xn
    transpose_ln_kernel<<<dim3(1024, 16), 256>>>(bufA, ln0g, ln0b, xn);

    // SRU layer 0 (k=4)
    mma_gemm_kernel<<<dim3(2, 128), 256, 4*GTW*4>>>(xn, wproj0, tmp, NROWS, 256, 2048);
    mma_gemm_kernel<<<dim3(32, 128), 256, 4*GTW*4>>>(tmp, w0, U, NROWS, 4096, 256);
    sru2_kernel<4><<<32, 512, 131072>>>(U, xn, vc0, bias0, sa);

    // SRU layers 1-3 (k=3)
    float* cur = sa;
    float* nxt = sb;
    for (int i = 0; i < 3; i++) {
        ln_kernel<<<NROWS, 256>>>(cur, lng + i*1024, lnb + i*1024, xn, 1024);
        mma_gemm_kernel<<<dim3(2, 128), 256, 4*GTW*4>>>(xn, wproj + (size_t)i*1024*256,
                                                        tmp, NROWS, 256, 1024);
        mma_gemm_kernel<<<dim3(24, 128), 256, 4*GTW*4>>>(tmp, w + (size_t)i*256*3072,
                                                         U, NROWS, 3072, 256);
        sru2_kernel<3><<<32, 512, 131072>>>(U, xn, vc + i*2048, bias + i*2048, nxt);
        float* t2 = cur; cur = nxt; nxt = t2;
    }

    // final LN + classifier
    final_kernel<<<NROWS, 256>>>(cur, clng, clnb, clsw, (float*)d_out);
}

// round 6
// speedup vs baseline: 2.7448x; 1.2863x over previous
#include <cuda_runtime.h>
#include <cuda_fp16.h>
#include <math.h>
#include <stdint.h>

#define EPSV 1e-5f

// ---- dims ----
#define BB   16
#define CC   32
#define FF   64
#define TT   1024
#define LL   1024
#define HH   512
#define PP   256
#define FEAT2 2048
#define DD   1024
#define NROWS (LL*BB)   // 16384

extern __shared__ char dynsmem[];

// ---- scratch (device globals; allocation-free) ----
__device__ float g_bufA[BB*CC*FF*TT];      // NHWC fp32
__device__ float g_bufB[BB*CC*FF*TT];
__device__ float g_xn[NROWS*FEAT2];        // fp32 LN out (rx path)
__device__ float g_xnT[NROWS*FEAT2];       // tf32-rounded LN out (GEMM A)
__device__ float g_tmp[NROWS*PP];          // GEMM1 out (tf32-rounded)
__device__ float g_U[NROWS*4096];
__device__ float g_sa[NROWS*DD];
__device__ float g_sb[NROWS*DD];
__device__ uint32_t g_w1[144*40];          // conv fp16 hi weights
__device__ uint32_t g_w2[144*40];          // conv fp16 lo weights
__device__ float g_bias2[CC];
__device__ uint32_t g_h1A[BB*FF*TT*16];    // packed fp16-hi activations (NHWC pairs)
__device__ uint32_t g_h2A[BB*FF*TT*16];    // packed fp16-lo
__device__ uint32_t g_h1B[BB*FF*TT*16];
__device__ uint32_t g_h2B[BB*FF*TT*16];
__device__ float g_wpT[FEAT2*PP];          // tf32-rounded proj weight (max 2048*256)
__device__ float g_wwT[PP*4096];           // tf32-rounded main weight (max 256*4096)

__device__ __forceinline__ void cpa16(void* smem, const void* gmem) {
    uint32_t s = (uint32_t)__cvta_generic_to_shared(smem);
    asm volatile("cp.async.cg.shared.global [%0], [%1], 16;\n" :: "r"(s), "l"(gmem));
}
__device__ __forceinline__ void cpa16z(void* smem, const void* gmem, bool ok) {
    uint32_t s = (uint32_t)__cvta_generic_to_shared(smem);
    int sz = ok ? 16 : 0;
    asm volatile("cp.async.cg.shared.global [%0], [%1], 16, %2;\n" :: "r"(s), "l"(gmem), "r"(sz));
}

__device__ __forceinline__ uint32_t f2tf(float x) {
    uint32_t u;
    asm("cvt.rna.tf32.f32 %0, %1;" : "=r"(u) : "f"(x));
    return u;
}

__device__ __forceinline__ uint32_t packhi(float a, float b) {
    __half2 h = __halves2half2(__float2half_rn(a), __float2half_rn(b));
    return *(uint32_t*)&h;
}
__device__ __forceinline__ uint32_t packlo(float a, float b) {
    __half ha = __float2half_rn(a), hb = __float2half_rn(b);
    __half2 l = __halves2half2(__float2half_rn(a - __half2float(ha)),
                               __float2half_rn(b - __half2float(hb)));
    return *(uint32_t*)&l;
}

// ============================================================
// tf32 rounding copy (weights / staging elimination)
// ============================================================
__global__ void tf32_round_kernel(const float4* __restrict__ in,
                                  float4* __restrict__ out, int n4) {
    int i = blockIdx.x * blockDim.x + threadIdx.x;
    if (i < n4) {
        float4 v = in[i];
        v.x = __uint_as_float(f2tf(v.x));
        v.y = __uint_as_float(f2tf(v.y));
        v.z = __uint_as_float(f2tf(v.z));
        v.w = __uint_as_float(f2tf(v.w));
        out[i] = v;
    }
}

// ============================================================
// conv0: x(16,1,128,2048) -> NHWC fp32 + packed fp16 hi/lo
// ============================================================
__global__ void conv0_kernel(const float* __restrict__ x,
                             const float* __restrict__ w,
                             const float* __restrict__ cb,
                             float* __restrict__ out,
                             uint32_t* __restrict__ oh1,
                             uint32_t* __restrict__ oh2) {
    __shared__ float ws[288];
    __shared__ float bs[32];
    int tid = threadIdx.x;
    for (int i = tid; i < 288; i += 256) {
        int co = i / 9, j = i % 9;
        ws[j*32 + co] = w[i];
    }
    if (tid < 32) bs[tid] = cb[tid];
    __syncthreads();

    int to = blockIdx.x * 256 + tid;
    int fo = blockIdx.y;
    int b  = blockIdx.z;

    float acc[32];
#pragma unroll
    for (int q = 0; q < 32; q++) acc[q] = bs[q];

#pragma unroll
    for (int df = 0; df < 3; df++) {
        int xi = 2*fo + df - 1;
        if (xi < 0 || xi >= 128) continue;
#pragma unroll
        for (int dt = 0; dt < 3; dt++) {
            int ti = 2*to + dt - 1;
            if (ti < 0 || ti >= 2048) continue;
            float v = x[((size_t)b*128 + xi)*2048 + ti];
            int j = df*3 + dt;
#pragma unroll
            for (int q = 0; q < 8; q++) {
                float4 w4 = *(const float4*)&ws[j*32 + q*4];
                acc[q*4+0] = fmaf(v, w4.x, acc[q*4+0]);
                acc[q*4+1] = fmaf(v, w4.y, acc[q*4+1]);
                acc[q*4+2] = fmaf(v, w4.z, acc[q*4+2]);
                acc[q*4+3] = fmaf(v, w4.w, acc[q*4+3]);
            }
        }
    }
    size_t pos = ((size_t)b*64 + fo)*1024 + to;
#pragma unroll
    for (int q = 0; q < 8; q++)
        *(float4*)&out[pos*32 + q*4] = make_float4(acc[q*4], acc[q*4+1], acc[q*4+2], acc[q*4+3]);

    uint32_t hw_[16], lw_[16];
#pragma unroll
    for (int p = 0; p < 16; p++) {
        hw_[p] = packhi(acc[2*p], acc[2*p+1]);
        lw_[p] = packlo(acc[2*p], acc[2*p+1]);
    }
#pragma unroll
    for (int q = 0; q < 4; q++) {
        *(uint4*)&oh1[pos*16 + q*4] = *(uint4*)&hw_[q*4];
        *(uint4*)&oh2[pos*16 + q*4] = *(uint4*)&lw_[q*4];
    }
}

// ============================================================
// prep: fold BN into conv weights, split fp16 hi/lo
// ============================================================
__global__ void prep_conv_kernel(const float* __restrict__ w,
                                 const float* __restrict__ cb,
                                 const float* __restrict__ g,
                                 const float* __restrict__ beta,
                                 const float* __restrict__ m,
                                 const float* __restrict__ v,
                                 uint32_t* __restrict__ w1,
                                 uint32_t* __restrict__ w2,
                                 float* __restrict__ bias2) {
    int i = blockIdx.x * blockDim.x + threadIdx.x;
    if (i < 4608) {
        int co  = i & 31;
        int kk  = i >> 5;
        int j   = kk >> 4;
        int ci2 = kk & 15;
        float scale = g[co] * rsqrtf(v[co] + EPSV);
        float f0 = w[co*288 + (2*ci2    )*9 + j] * scale;
        float f1 = w[co*288 + (2*ci2 + 1)*9 + j] * scale;
        w1[kk*40 + co] = packhi(f0, f1);
        w2[kk*40 + co] = packlo(f0, f1);
    }
    if (i < 32) {
        float scale = g[i] * rsqrtf(v[i] + EPSV);
        bias2[i] = beta[i] + (cb[i] - m[i]) * scale;
    }
}

// ============================================================
// residual conv via fp16x3 mma; inputs pre-split packed fp16
// ============================================================
__device__ __forceinline__ void mma_f16(float* c, const uint32_t* a, const uint32_t* b) {
    asm volatile(
        "mma.sync.aligned.m16n8k16.row.col.f32.f16.f16.f32 "
        "{%0,%1,%2,%3}, {%4,%5,%6,%7}, {%8,%9}, {%0,%1,%2,%3};\n"
        : "+f"(c[0]), "+f"(c[1]), "+f"(c[2]), "+f"(c[3])
        : "r"(a[0]), "r"(a[1]), "r"(a[2]), "r"(a[3]),
          "r"(b[0]), "r"(b[1]));
}

#define RC_A1 0            // [3][130][20]
#define RC_A2 7800
#define RC_W1 15600        // [144][40]
#define RC_W2 21360
#define RC_WORDS 27120

__global__ __launch_bounds__(256)
void resconv_mma_kernel(const uint32_t* __restrict__ ih1,
                        const uint32_t* __restrict__ ih2,
                        const uint32_t* __restrict__ w1g,
                        const uint32_t* __restrict__ w2g,
                        const float* __restrict__ bias2,
                        const float* __restrict__ res,
                        float* __restrict__ out,
                        uint32_t* __restrict__ oh1,
                        uint32_t* __restrict__ oh2) {
    uint32_t* sm = (uint32_t*)dynsmem;
    uint32_t* A1 = sm + RC_A1;
    uint32_t* A2 = sm + RC_A2;
    uint32_t* W1 = sm + RC_W1;
    uint32_t* W2 = sm + RC_W2;
    __shared__ float bs[32];

    int tid = threadIdx.x;
    int t0 = blockIdx.x * 128;
    int f  = blockIdx.y;
    int b  = blockIdx.z;

    if (tid < 32) bs[tid] = bias2[tid];

    // weights via cp.async (1440 granules x2)
    for (int i = tid; i < 1440; i += 256) {
        cpa16(W1 + i*4, w1g + i*4);
        cpa16(W2 + i*4, w2g + i*4);
    }

    // activation slabs via cp.async with zero-fill halos
    for (int idx = tid; idx < 1560; idx += 256) {
        int df  = idx / 520;
        int rem = idx - df*520;
        int r = rem >> 2, gq = rem & 3;
        int xi = f + df - 1;
        int t  = t0 - 1 + r;
        bool ok = (xi >= 0) && (xi < 64) && (t >= 0) && (t < 1024);
        size_t off = ok ? ((((size_t)b*64 + xi)*1024 + t)*16 + gq*4) : 0;
        int dst = df*2600 + r*20 + gq*4;
        cpa16z(A1 + dst, ih1 + off, ok);
        cpa16z(A2 + dst, ih2 + off, ok);
    }
    asm volatile("cp.async.commit_group;\n");
    asm volatile("cp.async.wait_group 0;\n");
    __syncthreads();

    int lane = tid & 31, warp = tid >> 5;
    int g = lane >> 2, tg = lane & 3;
    int rowA = warp * 16;

    float acc[4][4];
#pragma unroll
    for (int nt = 0; nt < 4; nt++)
#pragma unroll
        for (int i = 0; i < 4; i++) acc[nt][i] = 0.f;

#pragma unroll
    for (int j = 0; j < 9; j++) {
        const int df = j / 3, dt = j % 3;
        const uint32_t* a1s = A1 + df*2600 + (rowA + dt)*20;
        const uint32_t* a2s = A2 + df*2600 + (rowA + dt)*20;
        const uint32_t* w1s = W1 + (j*16)*40;
        const uint32_t* w2s = W2 + (j*16)*40;
#pragma unroll
        for (int h = 0; h < 2; h++) {
            int kb = h*8;
            uint32_t a1f[4], a2f[4];
            a1f[0] = a1s[(g    )*20 + kb + tg];
            a1f[1] = a1s[(g + 8)*20 + kb + tg];
            a1f[2] = a1s[(g    )*20 + kb + tg + 4];
            a1f[3] = a1s[(g + 8)*20 + kb + tg + 4];
            a2f[0] = a2s[(g    )*20 + kb + tg];
            a2f[1] = a2s[(g + 8)*20 + kb + tg];
            a2f[2] = a2s[(g    )*20 + kb + tg + 4];
            a2f[3] = a2s[(g + 8)*20 + kb + tg + 4];
#pragma unroll
            for (int nt = 0; nt < 4; nt++) {
                uint32_t b1f[2], b2f[2];
                b1f[0] = w1s[(kb + tg    )*40 + nt*8 + g];
                b1f[1] = w1s[(kb + tg + 4)*40 + nt*8 + g];
                b2f[0] = w2s[(kb + tg    )*40 + nt*8 + g];
                b2f[1] = w2s[(kb + tg + 4)*40 + nt*8 + g];
                mma_f16(acc[nt], a1f, b1f);
                mma_f16(acc[nt], a2f, b1f);
                mma_f16(acc[nt], a1f, b2f);
            }
        }
    }

    // epilogue: bias (+res) relu, fp32 out; pack hi/lo via SMEM for coalescing
    bool hasres = (res != nullptr);
    bool hash   = (oh1 != nullptr);
    __syncthreads();   // done reading A1/A2; reuse as pack staging

    float vv[4][4];
#pragma unroll
    for (int nt = 0; nt < 4; nt++) {
        int co = nt*8 + tg*2;
#pragma unroll
        for (int half = 0; half < 2; half++) {
            int t = t0 + rowA + g + half*8;
            size_t addr = (((size_t)b*64 + f)*1024 + t)*32 + co;
            float v0 = acc[nt][half*2 + 0] + bs[co];
            float v1 = acc[nt][half*2 + 1] + bs[co + 1];
            if (hasres) {
                float2 rv = *(const float2*)(res + addr);
                v0 += rv.x; v1 += rv.y;
            }
            v0 = fmaxf(v0, 0.f); v1 = fmaxf(v1, 0.f);
            *(float2*)(out + addr) = make_float2(v0, v1);
            vv[nt][half*2]   = v0;
            vv[nt][half*2+1] = v1;
        }
    }

    if (hash) {
#pragma unroll
        for (int nt = 0; nt < 4; nt++) {
#pragma unroll
            for (int half = 0; half < 2; half++) {
                int tl = rowA + g + half*8;
                int wd = nt*4 + tg;
                A1[tl*20 + wd] = packhi(vv[nt][half*2], vv[nt][half*2+1]);
                A2[tl*20 + wd] = packlo(vv[nt][half*2], vv[nt][half*2+1]);
            }
        }
        __syncthreads();
        size_t posb = ((size_t)b*64 + f)*1024 + t0;
#pragma unroll
        for (int l = 0; l < 2; l++) {
            int idx = tid + l*256;          // 512 uint4
            int r = idx >> 2, q = idx & 3;
            *(uint4*)&oh1[(posb + r)*16 + q*4] = *(uint4*)&A1[r*20 + q*4];
            *(uint4*)&oh2[(posb + r)*16 + q*4] = *(uint4*)&A2[r*20 + q*4];
        }
    }
}

// ============================================================
// fused transpose + LN(2048) -> xnT (tf32-rounded)
// ============================================================
__global__ void transpose_ln_kernel(const float* __restrict__ in,
                                    const float* __restrict__ g,
                                    const float* __restrict__ bb,
                                    float* __restrict__ outT) {
    __shared__ float tile[64][33];
    __shared__ float rs[256], rs2[256];
    int t = blockIdx.x, b = blockIdx.y;
    int tid = threadIdx.x;
    float s = 0.f, s2 = 0.f;
    for (int i = tid; i < 512; i += 256) {
        int fq = i >> 3, c4 = (i & 7)*4;
        float4 v = *(const float4*)(in + (((size_t)b*64 + fq)*1024 + t)*32 + c4);
        tile[fq][c4]   = v.x; tile[fq][c4+1] = v.y;
        tile[fq][c4+2] = v.z; tile[fq][c4+3] = v.w;
        s  += v.x + v.y + v.z + v.w;
        s2 += v.x*v.x + v.y*v.y + v.z*v.z + v.w*v.w;
    }
    rs[tid] = s; rs2[tid] = s2;
    __syncthreads();
    for (int o = 128; o > 0; o >>= 1) {
        if (tid < o) { rs[tid] += rs[tid+o]; rs2[tid] += rs2[tid+o]; }
        __syncthreads();
    }
    float mean = rs[0] * (1.f/2048.f);
    float var  = rs2[0] * (1.f/2048.f) - mean*mean;
    float inv  = rsqrtf(var + EPSV);

    size_t ob = ((size_t)t*16 + b)*2048;
    for (int i = tid; i < 2048; i += 256) {
        int c = i >> 6, ff = i & 63;
        float vv = (tile[ff][c] - mean)*inv*g[i] + bb[i];
        outT[ob + i] = __uint_as_float(f2tf(vv));
    }
}

// ============================================================
// LayerNorm (W=1024) writing fp32 (rx) + tf32 (GEMM A)
// ============================================================
__global__ void ln_kernel(const float* __restrict__ in,
                          const float* __restrict__ g,
                          const float* __restrict__ bb,
                          float* __restrict__ out,
                          float* __restrict__ outT) {
    const int W = 1024;
    int row = blockIdx.x;
    int tid = threadIdx.x;
    const float* x = in + (size_t)row * W;

    float4 v4 = *(const float4*)(x + tid*4);
    float s  = v4.x + v4.y + v4.z + v4.w;
    float s2 = v4.x*v4.x + v4.y*v4.y + v4.z*v4.z + v4.w*v4.w;

    __shared__ float rs[256], rs2[256];
    rs[tid] = s; rs2[tid] = s2;
    __syncthreads();
    for (int o = 128; o > 0; o >>= 1) {
        if (tid < o) { rs[tid] += rs[tid+o]; rs2[tid] += rs2[tid+o]; }
        __syncthreads();
    }
    float mean = rs[0] * (1.f/1024.f);
    float var  = rs2[0] * (1.f/1024.f) - mean * mean;
    float inv  = rsqrtf(var + EPSV);

    int i = tid*4;
    float4 gg = *(const float4*)(g + i);
    float4 bv = *(const float4*)(bb + i);
    float4 r;
    r.x = (v4.x - mean)*inv*gg.x + bv.x;
    r.y = (v4.y - mean)*inv*gg.y + bv.y;
    r.z = (v4.z - mean)*inv*gg.z + bv.z;
    r.w = (v4.w - mean)*inv*gg.w + bv.w;
    *(float4*)(out + (size_t)row*W + i) = r;
    float4 rt;
    rt.x = __uint_as_float(f2tf(r.x));
    rt.y = __uint_as_float(f2tf(r.y));
    rt.z = __uint_as_float(f2tf(r.z));
    rt.w = __uint_as_float(f2tf(r.w));
    *(float4*)(outT + (size_t)row*W + i) = rt;
}

// ============================================================
// TF32 GEMM v3: operands pre-rounded; pure cp.async pipeline
// BM=128,BN=128,BK=32; A smem [m][36], B smem [k][136]
// ============================================================
__device__ __forceinline__ void mma_tf32(float* c, const uint32_t* a, const uint32_t* b) {
    asm volatile(
        "mma.sync.aligned.m16n8k8.row.col.f32.tf32.tf32.f32 "
        "{%0,%1,%2,%3}, {%4,%5,%6,%7}, {%8,%9}, {%0,%1,%2,%3};\n"
        : "+f"(c[0]), "+f"(c[1]), "+f"(c[2]), "+f"(c[3])
        : "r"(a[0]), "r"(a[1]), "r"(a[2]), "r"(a[3]),
          "r"(b[0]), "r"(b[1]));
}

#define GA_WORDS (128*36)          // 4608
#define GB_WORDS (32*136)          // 4352
#define GBUF (GA_WORDS + GB_WORDS) // 8960 words/stage; 2 stages = 71680 B

__global__ __launch_bounds__(256)
void mma_gemm_kernel(const float* __restrict__ A,
                     const float* __restrict__ Bm,
                     float* __restrict__ Cm,
                     int M, int N, int K, int round_out) {
    uint32_t* gsm = (uint32_t*)dynsmem;

    int tid  = threadIdx.x;
    int lane = tid & 31, warp = tid >> 5;
    int m0 = blockIdx.y * 128, n0 = blockIdx.x * 128;
    int wm = (warp >> 1) * 32;
    int wn = (warp & 1) * 64;
    int g  = lane >> 2, tg = lane & 3;

    float acc[2][8][4];
#pragma unroll
    for (int mt = 0; mt < 2; mt++)
#pragma unroll
        for (int nt = 0; nt < 8; nt++)
#pragma unroll
            for (int i = 0; i < 4; i++) acc[mt][nt][i] = 0.f;

#define GEMM_STAGE(k0_, buf_) do {                                            \
    uint32_t* as_ = gsm + (buf_)*GBUF;                                        \
    uint32_t* bs_ = as_ + GA_WORDS;                                           \
    _Pragma("unroll")                                                         \
    for (int l = 0; l < 4; l++) {                                             \
        int idx = tid + l*256;                                                \
        int r = idx >> 3, gq = idx & 7;                                       \
        cpa16(as_ + r*36 + gq*4, A + (size_t)(m0 + r)*K + (k0_) + gq*4);      \
    }                                                                         \
    _Pragma("unroll")                                                         \
    for (int l = 0; l < 4; l++) {                                             \
        int idx = tid + l*256;                                                \
        int r = idx >> 5, gq = idx & 31;                                      \
        cpa16(bs_ + r*136 + gq*4, Bm + (size_t)((k0_) + r)*N + n0 + gq*4);    \
    }                                                                         \
    asm volatile("cp.async.commit_group;\n");                                 \
} while (0)

    GEMM_STAGE(0, 0);

    int cur = 0;
    for (int k0 = 0; k0 < K; k0 += 32) {
        bool hn = (k0 + 32) < K;
        if (hn) {
            GEMM_STAGE(k0 + 32, cur ^ 1);
            asm volatile("cp.async.wait_group 1;\n");
        } else {
            asm volatile("cp.async.wait_group 0;\n");
        }
        __syncthreads();

        const uint32_t* asc = gsm + cur*GBUF;
        const uint32_t* bsc = asc + GA_WORDS;

#pragma unroll
        for (int kc = 0; kc < 4; kc++) {
            int kb = kc * 8;
            uint32_t af[2][4];
#pragma unroll
            for (int mt = 0; mt < 2; mt++) {
                int row = wm + mt*16 + g;
                af[mt][0] = asc[(row    )*36 + kb + tg];
                af[mt][1] = asc[(row + 8)*36 + kb + tg];
                af[mt][2] = asc[(row    )*36 + kb + tg + 4];
                af[mt][3] = asc[(row + 8)*36 + kb + tg + 4];
            }
            uint32_t bf[8][2];
#pragma unroll
            for (int nt = 0; nt < 8; nt++) {
                int col = wn + nt*8 + g;
                bf[nt][0] = bsc[(kb + tg    )*136 + col];
                bf[nt][1] = bsc[(kb + tg + 4)*136 + col];
            }
#pragma unroll
            for (int mt = 0; mt < 2; mt++)
#pragma unroll
                for (int nt = 0; nt < 8; nt++)
                    mma_tf32(acc[mt][nt], af[mt], bf[nt]);
        }
        __syncthreads();
        cur ^= 1;
    }
#undef GEMM_STAGE

#pragma unroll
    for (int mt = 0; mt < 2; mt++) {
        int row = m0 + wm + mt*16 + g;
#pragma unroll
        for (int nt = 0; nt < 8; nt++) {
            int col = n0 + wn + nt*8 + tg*2;
            float o0 = acc[mt][nt][0], o1 = acc[mt][nt][1];
            float o2 = acc[mt][nt][2], o3 = acc[mt][nt][3];
            if (round_out) {
                o0 = __uint_as_float(f2tf(o0)); o1 = __uint_as_float(f2tf(o1));
                o2 = __uint_as_float(f2tf(o2)); o3 = __uint_as_float(f2tf(o3));
            }
            *(float2*)&Cm[(size_t)row * N + col]       = make_float2(o0, o1);
            *(float2*)&Cm[(size_t)(row + 8) * N + col] = make_float2(o2, o3);
        }
    }
}

// ============================================================
// SRU: block per (d,b), 512 thr, cp.async 8-step chunks
// ============================================================
__device__ __forceinline__ float sigmf(float x) {
    return __fdividef(1.f, 1.f + __expf(-x));
}

template <int KK>
__global__ __launch_bounds__(512)
void sru2_kernel(const float* __restrict__ U,
                 const float* __restrict__ xn,
                 const float* __restrict__ vc,
                 const float* __restrict__ bias,
                 float* __restrict__ out) {
    float* sm = (float*)dynsmem;
    const int USTEP = KK*512;
    float* ub = sm;
    float* xb = sm + 2*8*USTEP;

    const int j = threadIdx.x;
    const int d = blockIdx.x >> 4;
    const int b = blockIdx.x & 15;
    const int RW = 2*KK*512;

    float vf = vc[d*1024 + j],   vr = vc[d*1024 + 512 + j];
    float bf = bias[d*1024 + j], br = bias[d*1024 + 512 + j];

#define SRU_LOAD_CHUNK(cc, buf) do {                                          \
    int s0 = (cc)*8;                                                          \
    for (int idx = j; idx < 8*KK*128; idx += 512) {                           \
        int i = idx / (KK*128);                                               \
        int o = idx - i*(KK*128);                                             \
        int t = d ? (1023 - (s0+i)) : (s0+i);                                 \
        const float* src = U + ((size_t)t*16 + b)*RW + d*USTEP + o*4;         \
        cpa16(ub + ((buf)*8 + i)*USTEP + o*4, src);                           \
    }                                                                         \
    if (KK == 3) {                                                            \
        for (int idx = j; idx < 1024; idx += 512) {                           \
            int i = idx >> 7;                                                 \
            int o = idx & 127;                                                \
            int t = d ? (1023 - (s0+i)) : (s0+i);                             \
            const float* src = xn + ((size_t)t*16 + b)*1024 + d*512 + o*4;    \
            cpa16(xb + ((buf)*8 + i)*512 + o*4, src);                         \
        }                                                                     \
    }                                                                         \
    asm volatile("cp.async.commit_group;\n");                                 \
} while (0)

    SRU_LOAD_CHUNK(0, 0);

    float c = 0.f;
    for (int ch = 0; ch < 128; ch++) {
        int buf = ch & 1;
        if (ch < 127) {
            SRU_LOAD_CHUNK(ch + 1, buf ^ 1);
            asm volatile("cp.async.wait_group 1;\n");
        } else {
            asm volatile("cp.async.wait_group 0;\n");
        }
        __syncthreads();
#pragma unroll
        for (int i = 0; i < 8; i++) {
            int s = ch*8 + i;
            int t = d ? (1023 - s) : s;
            const float* us = ub + (buf*8 + i)*USTEP;
            float a0 = us[j], a1 = us[512 + j], a2 = us[1024 + j];
            float rx = (KK == 4) ? us[1536 + j] : xb[(buf*8 + i)*512 + j];
            float f = sigmf(fmaf(vf, c, a1) + bf);
            c = fmaf(f, c - a0, a0);
            float r = sigmf(fmaf(vr, c, a2) + br);
            out[((size_t)t*16 + b)*1024 + d*512 + j] = fmaf(r, c - rx, rx);
        }
        __syncthreads();
    }
#undef SRU_LOAD_CHUNK
}

// ============================================================
// final: per row LN(1024) + @cls_w(1024,30)
// ============================================================
__global__ void final_kernel(const float* __restrict__ s,
                             const float* __restrict__ g,
                             const float* __restrict__ bb,
                             const float* __restrict__ cw,
                             float* __restrict__ out) {
    int row = blockIdx.x;
    int t = row >> 4, b = row & 15;
    int tid = threadIdx.x;
    const float* x = s + (size_t)row * 1024;

    float4 v4 = *(const float4*)(x + tid*4);
    float sm = v4.x + v4.y + v4.z + v4.w;
    float s2 = v4.x*v4.x + v4.y*v4.y + v4.z*v4.z + v4.w*v4.w;

    __shared__ float rs[256], rs2[256];
    rs[tid] = sm; rs2[tid] = s2;
    __syncthreads();
    for (int o = 128; o > 0; o >>= 1) {
        if (tid < o) { rs[tid] += rs[tid+o]; rs2[tid] += rs2[tid+o]; }
        __syncthreads();
    }
    float mean = rs[0] * (1.f/1024.f);
    float var  = rs2[0] * (1.f/1024.f) - mean*mean;
    float inv  = rsqrtf(var + EPSV);

    float acc[30];
#pragma unroll
    for (int k = 0; k < 30; k++) acc[k] = 0.f;

    for (int dd = tid; dd < 1024; dd += 256) {
        float v = (x[dd] - mean)*inv*g[dd] + bb[dd];
        const float* cwr = cw + dd*30;
#pragma unroll
        for (int k = 0; k < 30; k++)
            acc[k] = fmaf(v, cwr[k], acc[k]);
    }

    __shared__ float sacc[30];
    if (tid < 30) sacc[tid] = 0.f;
    __syncthreads();
#pragma unroll
    for (int k = 0; k < 30; k++) {
        float v = acc[k];
#pragma unroll
        for (int o = 16; o > 0; o >>= 1)
            v += __shfl_down_sync(0xffffffffu, v, o);
        if ((tid & 31) == 0) atomicAdd(&sacc[k], v);
    }
    __syncthreads();
    if (tid < 30)
        out[((size_t)b*1024 + t)*30 + tid] = sacc[tid];
}

// ============================================================
// host orchestration
// ============================================================
extern "C" void kernel_launch(void* const* d_in, const int* in_sizes, int n_in,
                              void* d_out, int out_size) {
    const float* x       = (const float*)d_in[0];
    const float* conv0_w = (const float*)d_in[1];
    const float* conv0_b = (const float*)d_in[2];
    const float* rc1w = (const float*)d_in[3];
    const float* rc1b = (const float*)d_in[4];
    const float* rb1g = (const float*)d_in[5];
    const float* rb1b = (const float*)d_in[6];
    const float* rb1m = (const float*)d_in[7];
    const float* rb1v = (const float*)d_in[8];
    const float* rc2w = (const float*)d_in[9];
    const float* rc2b = (const float*)d_in[10];
    const float* rb2g = (const float*)d_in[11];
    const float* rb2b = (const float*)d_in[12];
    const float* rb2m = (const float*)d_in[13];
    const float* rb2v = (const float*)d_in[14];
    const float* ln0g = (const float*)d_in[15];
    const float* ln0b = (const float*)d_in[16];
    const float* wproj0 = (const float*)d_in[17];
    const float* w0   = (const float*)d_in[18];
    const float* vc0  = (const float*)d_in[19];
    const float* bias0= (const float*)d_in[20];
    const float* lng  = (const float*)d_in[21];
    const float* lnb  = (const float*)d_in[22];
    const float* wproj= (const float*)d_in[23];
    const float* w    = (const float*)d_in[24];
    const float* vc   = (const float*)d_in[25];
    const float* bias = (const float*)d_in[26];
    const float* clng = (const float*)d_in[27];
    const float* clnb = (const float*)d_in[28];
    const float* clsw = (const float*)d_in[29];

    float *bufA, *bufB, *xn, *xnT, *tmp, *U, *sa, *sb, *bias2, *wpT, *wwT;
    uint32_t *w1, *w2, *h1A, *h2A, *h1B, *h2B;
    cudaGetSymbolAddress((void**)&bufA,  g_bufA);
    cudaGetSymbolAddress((void**)&bufB,  g_bufB);
    cudaGetSymbolAddress((void**)&xn,    g_xn);
    cudaGetSymbolAddress((void**)&xnT,   g_xnT);
    cudaGetSymbolAddress((void**)&tmp,   g_tmp);
    cudaGetSymbolAddress((void**)&U,     g_U);
    cudaGetSymbolAddress((void**)&sa,    g_sa);
    cudaGetSymbolAddress((void**)&sb,    g_sb);
    cudaGetSymbolAddress((void**)&w1,    g_w1);
    cudaGetSymbolAddress((void**)&w2,    g_w2);
    cudaGetSymbolAddress((void**)&bias2, g_bias2);
    cudaGetSymbolAddress((void**)&h1A,   g_h1A);
    cudaGetSymbolAddress((void**)&h2A,   g_h2A);
    cudaGetSymbolAddress((void**)&h1B,   g_h1B);
    cudaGetSymbolAddress((void**)&h2B,   g_h2B);
    cudaGetSymbolAddress((void**)&wpT,   g_wpT);
    cudaGetSymbolAddress((void**)&wwT,   g_wwT);

    cudaFuncSetAttribute(resconv_mma_kernel,
                         cudaFuncAttributeMaxDynamicSharedMemorySize, RC_WORDS*4);
    cudaFuncSetAttribute(mma_gemm_kernel,
                         cudaFuncAttributeMaxDynamicSharedMemorySize, 2*GBUF*4);
    cudaFuncSetAttribute(sru2_kernel<4>,
                         cudaFuncAttributeMaxDynamicSharedMemorySize, 131072);
    cudaFuncSetAttribute(sru2_kernel<3>,
                         cudaFuncAttributeMaxDynamicSharedMemorySize, 131072);

    // conv front-end
    conv0_kernel<<<dim3(4, 64, 16), 256>>>(x, conv0_w, conv0_b, bufA, h1A, h2A);

    dim3 rcgrid(8, 64, 16);
    for (int i = 0; i < 3; i++) {
        prep_conv_kernel<<<5, 1024>>>(rc1w + i*9216, rc1b + i*32,
                                      rb1g + i*32, rb1b + i*32,
                                      rb1m + i*32, rb1v + i*32, w1, w2, bias2);
        resconv_mma_kernel<<<rcgrid, 256, RC_WORDS*4>>>(h1A, h2A, w1, w2, bias2,
                                                        nullptr, bufB, h1B, h2B);
        prep_conv_kernel<<<5, 1024>>>(rc2w + i*9216, rc2b + i*32,
                                      rb2g + i*32, rb2b + i*32,
                                      rb2m + i*32, rb2v + i*32, w1, w2, bias2);
        resconv_mma_kernel<<<rcgrid, 256, RC_WORDS*4>>>(h1B, h2B, w1, w2, bias2,
                                                        bufA, bufA, h1A, h2A);
    }

    // fused transpose + LN(2048) -> xnT
    transpose_ln_kernel<<<dim3(1024, 16), 256>>>(bufA, ln0g, ln0b, xnT);

    // SRU layer 0 (k=4)
    tf32_round_kernel<<<512, 256>>>((const float4*)wproj0, (float4*)wpT, 131072);
    tf32_round_kernel<<<1024, 256>>>((const float4*)w0, (float4*)wwT, 262144);
    mma_gemm_kernel<<<dim3(2, 128), 256, 2*GBUF*4>>>(xnT, wpT, tmp, NROWS, 256, 2048, 1);
    mma_gemm_kernel<<<dim3(32, 128), 256, 2*GBUF*4>>>(tmp, wwT, U, NROWS, 4096, 256, 0);
    sru2_kernel<4><<<32, 512, 131072>>>(U, xn, vc0, bias0, sa);

    // SRU layers 1-3 (k=3)
    float* cur = sa;
    float* nxt = sb;
    for (int i = 0; i < 3; i++) {
        ln_kernel<<<NROWS, 256>>>(cur, lng + i*1024, lnb + i*1024, xn, xnT);
        tf32_round_kernel<<<256, 256>>>((const float4*)(wproj + (size_t)i*1024*256),
                                        (float4*)wpT, 65536);
        tf32_round_kernel<<<768, 256>>>((const float4*)(w + (size_t)i*256*3072),
                                        (float4*)wwT, 196608);
        mma_gemm_kernel<<<dim3(2, 128), 256, 2*GBUF*4>>>(xnT, wpT, tmp, NROWS, 256, 1024, 1);
        mma_gemm_kernel<<<dim3(24, 128), 256, 2*GBUF*4>>>(tmp, wwT, U, NROWS, 3072, 256, 0);
        sru2_kernel<3><<<32, 512, 131072>>>(U, xn, vc + i*2048, bias + i*2048, nxt);
        float* t2 = cur; cur = nxt; nxt = t2;
    }

    // final LN + classifier
    final_kernel<<<NROWS, 256>>>(cur, clng, clnb, clsw, (float*)d_out);
}

// round 7
// speedup vs baseline: 2.8585x; 1.0415x over previous
#include <cuda_runtime.h>
#include <cuda_fp16.h>
#include <math.h>
#include <stdint.h>

#define EPSV 1e-5f

// ---- dims ----
#define BB   16
#define CC   32
#define FF   64
#define TT   1024
#define LL   1024
#define HH   512
#define PP   256
#define FEAT2 2048
#define DD   1024
#define NROWS (LL*BB)   // 16384

extern __shared__ char dynsmem[];

// ---- scratch ----
__device__ float g_bufA[BB*CC*FF*TT];
__device__ float g_bufB[BB*CC*FF*TT];
__device__ float g_xn[NROWS*FEAT2];
__device__ float g_xnT[NROWS*FEAT2];       // k-permuted tf32 LN out
__device__ float g_tmp[NROWS*PP];          // k-permuted tf32 GEMM1 out
__device__ float g_U[NROWS*4096];
__device__ float g_sa[NROWS*DD];
__device__ float g_sb[NROWS*DD];
__device__ uint32_t g_w1[6*144*40];        // conv fp16 hi weights, 6 layers
__device__ uint32_t g_w2[6*144*40];
__device__ float g_bias2[6*32];
__device__ uint32_t g_h1A[BB*FF*TT*16];
__device__ uint32_t g_h2A[BB*FF*TT*16];
__device__ uint32_t g_h1B[BB*FF*TT*16];
__device__ uint32_t g_h2B[BB*FF*TT*16];
__device__ float g_wpT[2048*256 + 3*1024*256];   // transposed+permuted proj weights
__device__ float g_wwT[4096*256 + 3*3072*256];   // transposed+permuted main weights

__device__ __forceinline__ void cpa16(void* smem, const void* gmem) {
    uint32_t s = (uint32_t)__cvta_generic_to_shared(smem);
    asm volatile("cp.async.cg.shared.global [%0], [%1], 16;\n" :: "r"(s), "l"(gmem));
}
__device__ __forceinline__ void cpa16z(void* smem, const void* gmem, bool ok) {
    uint32_t s = (uint32_t)__cvta_generic_to_shared(smem);
    int sz = ok ? 16 : 0;
    asm volatile("cp.async.cg.shared.global [%0], [%1], 16, %2;\n" :: "r"(s), "l"(gmem), "r"(sz));
}
__device__ __forceinline__ uint32_t f2tf(float x) {
    uint32_t u;
    asm("cvt.rna.tf32.f32 %0, %1;" : "=r"(u) : "f"(x));
    return u;
}
// stored position of logical k within its 8-block: order 0,4,1,5,2,6,3,7
__device__ __forceinline__ int ksperm(int k) {
    return (k & ~7) | (((k & 3) << 1) | ((k >> 2) & 1));
}
__device__ __forceinline__ uint32_t packhi(float a, float b) {
    __half2 h = __halves2half2(__float2half_rn(a), __float2half_rn(b));
    return *(uint32_t*)&h;
}
__device__ __forceinline__ uint32_t packlo(float a, float b) {
    __half ha = __float2half_rn(a), hb = __float2half_rn(b);
    __half2 l = __halves2half2(__float2half_rn(a - __half2float(ha)),
                               __float2half_rn(b - __half2float(hb)));
    return *(uint32_t*)&l;
}

// ============================================================
// weight transpose + tf32 round + k-permute: W[K][N] -> WT[N][K']
// ============================================================
__global__ void trT_kernel(const float* __restrict__ W,
                           float* __restrict__ WT, int K, int N) {
    __shared__ float tile[32][33];
    int n0 = blockIdx.x*32, k0 = blockIdx.y*32;
    int tx = threadIdx.x, ty = threadIdx.y;  // (32,8)
#pragma unroll
    for (int i = 0; i < 4; i++)
        tile[ty + 8*i][tx] = W[(size_t)(k0 + ty + 8*i)*N + n0 + tx];
    __syncthreads();
    int kst = k0 + ksperm(tx);
#pragma unroll
    for (int i = 0; i < 4; i++) {
        int n = n0 + ty + 8*i;
        WT[(size_t)n*K + kst] = __uint_as_float(f2tf(tile[tx][ty + 8*i]));
    }
}

// ============================================================
// conv0 -> NHWC fp32 + packed fp16 hi/lo
// ============================================================
__global__ void conv0_kernel(const float* __restrict__ x,
                             const float* __restrict__ w,
                             const float* __restrict__ cb,
                             float* __restrict__ out,
                             uint32_t* __restrict__ oh1,
                             uint32_t* __restrict__ oh2) {
    __shared__ float ws[288];
    __shared__ float bs[32];
    int tid = threadIdx.x;
    for (int i = tid; i < 288; i += 256) {
        int co = i / 9, j = i % 9;
        ws[j*32 + co] = w[i];
    }
    if (tid < 32) bs[tid] = cb[tid];
    __syncthreads();

    int to = blockIdx.x * 256 + tid;
    int fo = blockIdx.y;
    int b  = blockIdx.z;

    float acc[32];
#pragma unroll
    for (int q = 0; q < 32; q++) acc[q] = bs[q];

#pragma unroll
    for (int df = 0; df < 3; df++) {
        int xi = 2*fo + df - 1;
        if (xi < 0 || xi >= 128) continue;
#pragma unroll
        for (int dt = 0; dt < 3; dt++) {
            int ti = 2*to + dt - 1;
            if (ti < 0 || ti >= 2048) continue;
            float v = x[((size_t)b*128 + xi)*2048 + ti];
            int j = df*3 + dt;
#pragma unroll
            for (int q = 0; q < 8; q++) {
                float4 w4 = *(const float4*)&ws[j*32 + q*4];
                acc[q*4+0] = fmaf(v, w4.x, acc[q*4+0]);
                acc[q*4+1] = fmaf(v, w4.y, acc[q*4+1]);
                acc[q*4+2] = fmaf(v, w4.z, acc[q*4+2]);
                acc[q*4+3] = fmaf(v, w4.w, acc[q*4+3]);
            }
        }
    }
    size_t pos = ((size_t)b*64 + fo)*1024 + to;
#pragma unroll
    for (int q = 0; q < 8; q++)
        *(float4*)&out[pos*32 + q*4] = make_float4(acc[q*4], acc[q*4+1], acc[q*4+2], acc[q*4+3]);

    uint32_t hw_[16], lw_[16];
#pragma unroll
    for (int p = 0; p < 16; p++) {
        hw_[p] = packhi(acc[2*p], acc[2*p+1]);
        lw_[p] = packlo(acc[2*p], acc[2*p+1]);
    }
#pragma unroll
    for (int q = 0; q < 4; q++) {
        *(uint4*)&oh1[pos*16 + q*4] = *(uint4*)&hw_[q*4];
        *(uint4*)&oh2[pos*16 + q*4] = *(uint4*)&lw_[q*4];
    }
}

// ============================================================
// prep ALL 6 conv layers in one launch (blockIdx.y = layer)
// ============================================================
__global__ void prep_conv_all_kernel(const float* __restrict__ rc1w,
                                     const float* __restrict__ rc1b,
                                     const float* __restrict__ rb1g,
                                     const float* __restrict__ rb1b,
                                     const float* __restrict__ rb1m,
                                     const float* __restrict__ rb1v,
                                     const float* __restrict__ rc2w,
                                     const float* __restrict__ rc2b,
                                     const float* __restrict__ rb2g,
                                     const float* __restrict__ rb2b,
                                     const float* __restrict__ rb2m,
                                     const float* __restrict__ rb2v,
                                     uint32_t* __restrict__ w1,
                                     uint32_t* __restrict__ w2,
                                     float* __restrict__ bias2) {
    int layer = blockIdx.y;
    int bi = layer >> 1, sec = layer & 1;
    const float* w   = (sec ? rc2w : rc1w) + bi*9216;
    const float* cb  = (sec ? rc2b : rc1b) + bi*32;
    const float* g   = (sec ? rb2g : rb1g) + bi*32;
    const float* bt  = (sec ? rb2b : rb1b) + bi*32;
    const float* m   = (sec ? rb2m : rb1m) + bi*32;
    const float* v   = (sec ? rb2v : rb1v) + bi*32;
    uint32_t* o1 = w1 + layer*5760;
    uint32_t* o2 = w2 + layer*5760;
    float* ob = bias2 + layer*32;

    int i = blockIdx.x * blockDim.x + threadIdx.x;
    if (i < 4608) {
        int co  = i & 31;
        int kk  = i >> 5;
        int j   = kk >> 4;
        int ci2 = kk & 15;
        float scale = g[co] * rsqrtf(v[co] + EPSV);
        float f0 = w[co*288 + (2*ci2    )*9 + j] * scale;
        float f1 = w[co*288 + (2*ci2 + 1)*9 + j] * scale;
        o1[kk*40 + co] = packhi(f0, f1);
        o2[kk*40 + co] = packlo(f0, f1);
    }
    if (i < 32) {
        float scale = g[i] * rsqrtf(v[i] + EPSV);
        ob[i] = bt[i] + (cb[i] - m[i]) * scale;
    }
}

// ============================================================
// residual conv via fp16x3 mma (unchanged structure)
// ============================================================
__device__ __forceinline__ void mma_f16(float* c, const uint32_t* a, const uint32_t* b) {
    asm volatile(
        "mma.sync.aligned.m16n8k16.row.col.f32.f16.f16.f32 "
        "{%0,%1,%2,%3}, {%4,%5,%6,%7}, {%8,%9}, {%0,%1,%2,%3};\n"
        : "+f"(c[0]), "+f"(c[1]), "+f"(c[2]), "+f"(c[3])
        : "r"(a[0]), "r"(a[1]), "r"(a[2]), "r"(a[3]),
          "r"(b[0]), "r"(b[1]));
}

#define RC_A1 0            // [3][130][20]
#define RC_A2 7800
#define RC_W1 15600        // [144][40]
#define RC_W2 21360
#define RC_WORDS 27120

__global__ __launch_bounds__(256)
void resconv_mma_kernel(const uint32_t* __restrict__ ih1,
                        const uint32_t* __restrict__ ih2,
                        const uint32_t* __restrict__ w1g,
                        const uint32_t* __restrict__ w2g,
                        const float* __restrict__ bias2,
                        const float* __restrict__ res,
                        float* __restrict__ out,
                        uint32_t* __restrict__ oh1,
                        uint32_t* __restrict__ oh2) {
    uint32_t* sm = (uint32_t*)dynsmem;
    uint32_t* A1 = sm + RC_A1;
    uint32_t* A2 = sm + RC_A2;
    uint32_t* W1 = sm + RC_W1;
    uint32_t* W2 = sm + RC_W2;
    __shared__ float bs[32];

    int tid = threadIdx.x;
    int t0 = blockIdx.x * 128;
    int f  = blockIdx.y;
    int b  = blockIdx.z;

    if (tid < 32) bs[tid] = bias2[tid];

    for (int i = tid; i < 1440; i += 256) {
        cpa16(W1 + i*4, w1g + i*4);
        cpa16(W2 + i*4, w2g + i*4);
    }
    for (int idx = tid; idx < 1560; idx += 256) {
        int df  = idx / 520;
        int rem = idx - df*520;
        int r = rem >> 2, gq = rem & 3;
        int xi = f + df - 1;
        int t  = t0 - 1 + r;
        bool ok = (xi >= 0) && (xi < 64) && (t >= 0) && (t < 1024);
        size_t off = ok ? ((((size_t)b*64 + xi)*1024 + t)*16 + gq*4) : 0;
        int dst = df*2600 + r*20 + gq*4;
        cpa16z(A1 + dst, ih1 + off, ok);
        cpa16z(A2 + dst, ih2 + off, ok);
    }
    asm volatile("cp.async.commit_group;\n");
    asm volatile("cp.async.wait_group 0;\n");
    __syncthreads();

    int lane = tid & 31, warp = tid >> 5;
    int g = lane >> 2, tg = lane & 3;
    int rowA = warp * 16;

    float acc[4][4];
#pragma unroll
    for (int nt = 0; nt < 4; nt++)
#pragma unroll
        for (int i = 0; i < 4; i++) acc[nt][i] = 0.f;

#pragma unroll
    for (int j = 0; j < 9; j++) {
        const int df = j / 3, dt = j % 3;
        const uint32_t* a1s = A1 + df*2600 + (rowA + dt)*20;
        const uint32_t* a2s = A2 + df*2600 + (rowA + dt)*20;
        const uint32_t* w1s = W1 + (j*16)*40;
        const uint32_t* w2s = W2 + (j*16)*40;
#pragma unroll
        for (int h = 0; h < 2; h++) {
            int kb = h*8;
            uint32_t a1f[4], a2f[4];
            a1f[0] = a1s[(g    )*20 + kb + tg];
            a1f[1] = a1s[(g + 8)*20 + kb + tg];
            a1f[2] = a1s[(g    )*20 + kb + tg + 4];
            a1f[3] = a1s[(g + 8)*20 + kb + tg + 4];
            a2f[0] = a2s[(g    )*20 + kb + tg];
            a2f[1] = a2s[(g + 8)*20 + kb + tg];
            a2f[2] = a2s[(g    )*20 + kb + tg + 4];
            a2f[3] = a2s[(g + 8)*20 + kb + tg + 4];
#pragma unroll
            for (int nt = 0; nt < 4; nt++) {
                uint32_t b1f[2], b2f[2];
                b1f[0] = w1s[(kb + tg    )*40 + nt*8 + g];
                b1f[1] = w1s[(kb + tg + 4)*40 + nt*8 + g];
                b2f[0] = w2s[(kb + tg    )*40 + nt*8 + g];
                b2f[1] = w2s[(kb + tg + 4)*40 + nt*8 + g];
                mma_f16(acc[nt], a1f, b1f);
                mma_f16(acc[nt], a2f, b1f);
                mma_f16(acc[nt], a1f, b2f);
            }
        }
    }

    bool hasres = (res != nullptr);
    bool hash   = (oh1 != nullptr);
    __syncthreads();

    float vv[4][4];
#pragma unroll
    for (int nt = 0; nt < 4; nt++) {
        int co = nt*8 + tg*2;
#pragma unroll
        for (int half = 0; half < 2; half++) {
            int t = t0 + rowA + g + half*8;
            size_t addr = (((size_t)b*64 + f)*1024 + t)*32 + co;
            float v0 = acc[nt][half*2 + 0] + bs[co];
            float v1 = acc[nt][half*2 + 1] + bs[co + 1];
            if (hasres) {
                float2 rv = *(const float2*)(res + addr);
                v0 += rv.x; v1 += rv.y;
            }
            v0 = fmaxf(v0, 0.f); v1 = fmaxf(v1, 0.f);
            *(float2*)(out + addr) = make_float2(v0, v1);
            vv[nt][half*2]   = v0;
            vv[nt][half*2+1] = v1;
        }
    }

    if (hash) {
#pragma unroll
        for (int nt = 0; nt < 4; nt++) {
#pragma unroll
            for (int half = 0; half < 2; half++) {
                int tl = rowA + g + half*8;
                int wd = nt*4 + tg;
                A1[tl*20 + wd] = packhi(vv[nt][half*2], vv[nt][half*2+1]);
                A2[tl*20 + wd] = packlo(vv[nt][half*2], vv[nt][half*2+1]);
            }
        }
        __syncthreads();
        size_t posb = ((size_t)b*64 + f)*1024 + t0;
#pragma unroll
        for (int l = 0; l < 2; l++) {
            int idx = tid + l*256;
            int r = idx >> 2, q = idx & 3;
            *(uint4*)&oh1[(posb + r)*16 + q*4] = *(uint4*)&A1[r*20 + q*4];
            *(uint4*)&oh2[(posb + r)*16 + q*4] = *(uint4*)&A2[r*20 + q*4];
        }
    }
}

// ============================================================
// fused transpose + LN(2048) -> xnT (tf32, k-permuted)
// ============================================================
__global__ void transpose_ln_kernel(const float* __restrict__ in,
                                    const float* __restrict__ g,
                                    const float* __restrict__ bb,
                                    float* __restrict__ outT) {
    __shared__ float tile[64][33];
    __shared__ float rs[256], rs2[256];
    int t = blockIdx.x, b = blockIdx.y;
    int tid = threadIdx.x;
    float s = 0.f, s2 = 0.f;
    for (int i = tid; i < 512; i += 256) {
        int fq = i >> 3, c4 = (i & 7)*4;
        float4 v = *(const float4*)(in + (((size_t)b*64 + fq)*1024 + t)*32 + c4);
        tile[fq][c4]   = v.x; tile[fq][c4+1] = v.y;
        tile[fq][c4+2] = v.z; tile[fq][c4+3] = v.w;
        s  += v.x + v.y + v.z + v.w;
        s2 += v.x*v.x + v.y*v.y + v.z*v.z + v.w*v.w;
    }
    rs[tid] = s; rs2[tid] = s2;
    __syncthreads();
    for (int o = 128; o > 0; o >>= 1) {
        if (tid < o) { rs[tid] += rs[tid+o]; rs2[tid] += rs2[tid+o]; }
        __syncthreads();
    }
    float mean = rs[0] * (1.f/2048.f);
    float var  = rs2[0] * (1.f/2048.f) - mean*mean;
    float inv  = rsqrtf(var + EPSV);

    size_t ob = ((size_t)t*16 + b)*2048;
    for (int i = tid; i < 2048; i += 256) {
        int c = i >> 6, ff = i & 63;
        float vv = (tile[ff][c] - mean)*inv*g[i] + bb[i];
        outT[ob + ksperm(i)] = __uint_as_float(f2tf(vv));
    }
}

// ============================================================
// LN(1024): fp32 (rx path) + tf32 k-permuted (GEMM A)
// ============================================================
__global__ void ln_kernel(const float* __restrict__ in,
                          const float* __restrict__ g,
                          const float* __restrict__ bb,
                          float* __restrict__ out,
                          float* __restrict__ outT) {
    const int W = 1024;
    int row = blockIdx.x;
    int tid = threadIdx.x;
    const float* x = in + (size_t)row * W;

    float4 v4 = *(const float4*)(x + tid*4);
    float s  = v4.x + v4.y + v4.z + v4.w;
    float s2 = v4.x*v4.x + v4.y*v4.y + v4.z*v4.z + v4.w*v4.w;

    __shared__ float rs[256], rs2[256];
    rs[tid] = s; rs2[tid] = s2;
    __syncthreads();
    for (int o = 128; o > 0; o >>= 1) {
        if (tid < o) { rs[tid] += rs[tid+o]; rs2[tid] += rs2[tid+o]; }
        __syncthreads();
    }
    float mean = rs[0] * (1.f/1024.f);
    float var  = rs2[0] * (1.f/1024.f) - mean * mean;
    float inv  = rsqrtf(var + EPSV);

    int i = tid*4;
    float4 gg = *(const float4*)(g + i);
    float4 bv = *(const float4*)(bb + i);
    float r0 = (v4.x - mean)*inv*gg.x + bv.x;
    float r1 = (v4.y - mean)*inv*gg.y + bv.y;
    float r2 = (v4.z - mean)*inv*gg.z + bv.z;
    float r3 = (v4.w - mean)*inv*gg.w + bv.w;
    *(float4*)(out + (size_t)row*W + i) = make_float4(r0, r1, r2, r3);
    float* oT = outT + (size_t)row*W;
    oT[ksperm(i  )] = __uint_as_float(f2tf(r0));
    oT[ksperm(i+1)] = __uint_as_float(f2tf(r1));
    oT[ksperm(i+2)] = __uint_as_float(f2tf(r2));
    oT[ksperm(i+3)] = __uint_as_float(f2tf(r3));
}

// ============================================================
// TF32 GEMM v4: k-interleaved operands, LDS.64 fragments
// A gmem [M][K'] permuted; BT gmem [N][K'] permuted
// smem: A [128][40], B [128 cols][40]; both conflict-free
// ============================================================
__device__ __forceinline__ void mma_tf32(float* c, const uint32_t* a, const uint32_t* b) {
    asm volatile(
        "mma.sync.aligned.m16n8k8.row.col.f32.tf32.tf32.f32 "
        "{%0,%1,%2,%3}, {%4,%5,%6,%7}, {%8,%9}, {%0,%1,%2,%3};\n"
        : "+f"(c[0]), "+f"(c[1]), "+f"(c[2]), "+f"(c[3])
        : "r"(a[0]), "r"(a[1]), "r"(a[2]), "r"(a[3]),
          "r"(b[0]), "r"(b[1]));
}

#define GA_WORDS (128*40)
#define GB_WORDS (128*40)
#define GBUF (GA_WORDS + GB_WORDS)   // 10240 words; 2 stages = 81920 B

__global__ __launch_bounds__(256)
void mma_gemm_kernel(const float* __restrict__ A,
                     const float* __restrict__ BT,
                     float* __restrict__ Cm,
                     int M, int N, int K, int round_out) {
    uint32_t* gsm = (uint32_t*)dynsmem;

    int tid  = threadIdx.x;
    int lane = tid & 31, warp = tid >> 5;
    int m0 = blockIdx.y * 128, n0 = blockIdx.x * 128;
    int wm = (warp >> 1) * 32;
    int wn = (warp & 1) * 64;
    int g  = lane >> 2, tg = lane & 3;

    float acc[2][8][4];
#pragma unroll
    for (int mt = 0; mt < 2; mt++)
#pragma unroll
        for (int nt = 0; nt < 8; nt++)
#pragma unroll
            for (int i = 0; i < 4; i++) acc[mt][nt][i] = 0.f;

#define GEMM_STAGE(k0_, buf_) do {                                            \
    uint32_t* as_ = gsm + (buf_)*GBUF;                                        \
    uint32_t* bs_ = as_ + GA_WORDS;                                           \
    _Pragma("unroll")                                                         \
    for (int l = 0; l < 4; l++) {                                             \
        int idx = tid + l*256;                                                \
        int r = idx >> 3, gq = idx & 7;                                       \
        cpa16(as_ + r*40 + gq*4, A + (size_t)(m0 + r)*K + (k0_) + gq*4);      \
    }                                                                         \
    _Pragma("unroll")                                                         \
    for (int l = 0; l < 4; l++) {                                             \
        int idx = tid + l*256;                                                \
        int c = idx >> 3, gq = idx & 7;                                       \
        cpa16(bs_ + c*40 + gq*4, BT + (size_t)(n0 + c)*K + (k0_) + gq*4);     \
    }                                                                         \
    asm volatile("cp.async.commit_group;\n");                                 \
} while (0)

    GEMM_STAGE(0, 0);

    int cur = 0;
    for (int k0 = 0; k0 < K; k0 += 32) {
        bool hn = (k0 + 32) < K;
        if (hn) {
            GEMM_STAGE(k0 + 32, cur ^ 1);
            asm volatile("cp.async.wait_group 1;\n");
        } else {
            asm volatile("cp.async.wait_group 0;\n");
        }
        __syncthreads();

        const uint32_t* asc = gsm + cur*GBUF;
        const uint32_t* bsc = asc + GA_WORDS;

#pragma unroll
        for (int kc = 0; kc < 4; kc++) {
            int kb = kc * 8;
            uint32_t af[2][4];
#pragma unroll
            for (int mt = 0; mt < 2; mt++) {
                int row = wm + mt*16 + g;
                uint2 aA = *(const uint2*)&asc[(row    )*40 + kb + 2*tg];
                uint2 aB = *(const uint2*)&asc[(row + 8)*40 + kb + 2*tg];
                af[mt][0] = aA.x; af[mt][2] = aA.y;
                af[mt][1] = aB.x; af[mt][3] = aB.y;
            }
            uint32_t bf[8][2];
#pragma unroll
            for (int nt = 0; nt < 8; nt++) {
                int col = wn + nt*8 + g;
                uint2 bb = *(const uint2*)&bsc[col*40 + kb + 2*tg];
                bf[nt][0] = bb.x; bf[nt][1] = bb.y;
            }
#pragma unroll
            for (int mt = 0; mt < 2; mt++)
#pragma unroll
                for (int nt = 0; nt < 8; nt++)
                    mma_tf32(acc[mt][nt], af[mt], bf[nt]);
        }
        __syncthreads();
        cur ^= 1;
    }
#undef GEMM_STAGE

#pragma unroll
    for (int mt = 0; mt < 2; mt++) {
        int row = m0 + wm + mt*16 + g;
#pragma unroll
        for (int nt = 0; nt < 8; nt++) {
            int base = n0 + wn + nt*8;
            float o0 = acc[mt][nt][0], o1 = acc[mt][nt][1];
            float o2 = acc[mt][nt][2], o3 = acc[mt][nt][3];
            if (round_out) {
                // permuted scalar stores (output feeds next GEMM's K axis)
                int p0 = ksperm(2*tg), p1 = ksperm(2*tg + 1);
                Cm[(size_t)row * N + base + p0]       = __uint_as_float(f2tf(o0));
                Cm[(size_t)row * N + base + p1]       = __uint_as_float(f2tf(o1));
                Cm[(size_t)(row + 8) * N + base + p0] = __uint_as_float(f2tf(o2));
                Cm[(size_t)(row + 8) * N + base + p1] = __uint_as_float(f2tf(o3));
            } else {
                int col = base + tg*2;
                *(float2*)&Cm[(size_t)row * N + col]       = make_float2(o0, o1);
                *(float2*)&Cm[(size_t)(row + 8) * N + col] = make_float2(o2, o3);
            }
        }
    }
}

// ============================================================
// SRU v3: block per (d,b,jhalf) = 64 blocks x 256 thr
// ============================================================
__device__ __forceinline__ float sigmf(float x) {
    return __fdividef(1.f, 1.f + __expf(-x));
}

template <int KK>
__global__ __launch_bounds__(256)
void sru2_kernel(const float* __restrict__ U,
                 const float* __restrict__ xn,
                 const float* __restrict__ vc,
                 const float* __restrict__ bias,
                 float* __restrict__ out) {
    float* sm = (float*)dynsmem;
    float* ub = sm;                       // [2][8][KK*256]
    float* xb = sm + 2*8*KK*256;          // [2][8][256] (KK==3)

    const int tj = threadIdx.x;
    const int bx = blockIdx.x;
    const int d  = bx >> 5;
    const int b  = (bx >> 1) & 15;
    const int jh = bx & 1;
    const int j  = jh*256 + tj;
    const int RW = 2*KK*512;

    float vf = vc[d*1024 + j],   vr = vc[d*1024 + 512 + j];
    float bf = bias[d*1024 + j], br = bias[d*1024 + 512 + j];

#define SRU_LOAD_CHUNK(cc, buf) do {                                          \
    int s0 = (cc)*8;                                                          \
    for (int idx = tj; idx < 8*KK*64; idx += 256) {                           \
        int i = idx / (KK*64);                                                \
        int o = idx - i*(KK*64);                                              \
        int gi = o >> 6, gw = o & 63;                                         \
        int t = d ? (1023 - (s0+i)) : (s0+i);                                 \
        const float* src = U + ((size_t)t*16 + b)*RW + d*KK*512               \
                             + gi*512 + jh*256 + gw*4;                        \
        cpa16(ub + ((size_t)((buf)*8 + i)*KK + gi)*256 + gw*4, src);          \
    }                                                                         \
    if (KK == 3) {                                                            \
        for (int idx = tj; idx < 512; idx += 256) {                           \
            int i = idx >> 6, gw = idx & 63;                                  \
            int t = d ? (1023 - (s0+i)) : (s0+i);                             \
            const float* src = xn + ((size_t)t*16 + b)*1024 + d*512           \
                                  + jh*256 + gw*4;                            \
            cpa16(xb + ((buf)*8 + i)*256 + gw*4, src);                        \
        }                                                                     \
    }                                                                         \
    asm volatile("cp.async.commit_group;\n");                                 \
} while (0)

    SRU_LOAD_CHUNK(0, 0);

    float c = 0.f;
    for (int ch = 0; ch < 128; ch++) {
        int buf = ch & 1;
        if (ch < 127) {
            SRU_LOAD_CHUNK(ch + 1, buf ^ 1);
            asm volatile("cp.async.wait_group 1;\n");
        } else {
            asm volatile("cp.async.wait_group 0;\n");
        }
        __syncthreads();
#pragma unroll
        for (int i = 0; i < 8; i++) {
            int s = ch*8 + i;
            int t = d ? (1023 - s) : s;
            const float* us = ub + (size_t)(buf*8 + i)*KK*256;
            float a0 = us[tj], a1 = us[256 + tj], a2 = us[512 + tj];
            float rx = (KK == 4) ? us[768 + tj] : xb[(buf*8 + i)*256 + tj];
            float f = sigmf(fmaf(vf, c, a1) + bf);
            c = fmaf(f, c - a0, a0);
            float r = sigmf(fmaf(vr, c, a2) + br);
            out[((size_t)t*16 + b)*1024 + d*512 + j] = fmaf(r, c - rx, rx);
        }
        __syncthreads();
    }
#undef SRU_LOAD_CHUNK
}

// ============================================================
// final: per row LN(1024) + @cls_w(1024,30)
// ============================================================
__global__ void final_kernel(const float* __restrict__ s,
                             const float* __restrict__ g,
                             const float* __restrict__ bb,
                             const float* __restrict__ cw,
                             float* __restrict__ out) {
    int row = blockIdx.x;
    int t = row >> 4, b = row & 15;
    int tid = threadIdx.x;
    const float* x = s + (size_t)row * 1024;

    float4 v4 = *(const float4*)(x + tid*4);
    float sm = v4.x + v4.y + v4.z + v4.w;
    float s2 = v4.x*v4.x + v4.y*v4.y + v4.z*v4.z + v4.w*v4.w;

    __shared__ float rs[256], rs2[256];
    rs[tid] = sm; rs2[tid] = s2;
    __syncthreads();
    for (int o = 128; o > 0; o >>= 1) {
        if (tid < o) { rs[tid] += rs[tid+o]; rs2[tid] += rs2[tid+o]; }
        __syncthreads();
    }
    float mean = rs[0] * (1.f/1024.f);
    float var  = rs2[0] * (1.f/1024.f) - mean*mean;
    float inv  = rsqrtf(var + EPSV);

    float acc[30];
#pragma unroll
    for (int k = 0; k < 30; k++) acc[k] = 0.f;

    for (int dd = tid; dd < 1024; dd += 256) {
        float v = (x[dd] - mean)*inv*g[dd] + bb[dd];
        const float* cwr = cw + dd*30;
#pragma unroll
        for (int k = 0; k < 30; k++)
            acc[k] = fmaf(v, cwr[k], acc[k]);
    }

    __shared__ float sacc[30];
    if (tid < 30) sacc[tid] = 0.f;
    __syncthreads();
#pragma unroll
    for (int k = 0; k < 30; k++) {
        float v = acc[k];
#pragma unroll
        for (int o = 16; o > 0; o >>= 1)
            v += __shfl_down_sync(0xffffffffu, v, o);
        if ((tid & 31) == 0) atomicAdd(&sacc[k], v);
    }
    __syncthreads();
    if (tid < 30)
        out[((size_t)b*1024 + t)*30 + tid] = sacc[tid];
}

// ============================================================
// host orchestration
// ============================================================
extern "C" void kernel_launch(void* const* d_in, const int* in_sizes, int n_in,
                              void* d_out, int out_size) {
    const float* x       = (const float*)d_in[0];
    const float* conv0_w = (const float*)d_in[1];
    const float* conv0_b = (const float*)d_in[2];
    const float* rc1w = (const float*)d_in[3];
    const float* rc1b = (const float*)d_in[4];
    const float* rb1g = (const float*)d_in[5];
    const float* rb1b = (const float*)d_in[6];
    const float* rb1m = (const float*)d_in[7];
    const float* rb1v = (const float*)d_in[8];
    const float* rc2w = (const float*)d_in[9];
    const float* rc2b = (const float*)d_in[10];
    const float* rb2g = (const float*)d_in[11];
    const float* rb2b = (const float*)d_in[12];
    const float* rb2m = (const float*)d_in[13];
    const float* rb2v = (const float*)d_in[14];
    const float* ln0g = (const float*)d_in[15];
    const float* ln0b = (const float*)d_in[16];
    const float* wproj0 = (const float*)d_in[17];
    const float* w0   = (const float*)d_in[18];
    const float* vc0  = (const float*)d_in[19];
    const float* bias0= (const float*)d_in[20];
    const float* lng  = (const float*)d_in[21];
    const float* lnb  = (const float*)d_in[22];
    const float* wproj= (const float*)d_in[23];
    const float* w    = (const float*)d_in[24];
    const float* vc   = (const float*)d_in[25];
    const float* bias = (const float*)d_in[26];
    const float* clng = (const float*)d_in[27];
    const float* clnb = (const float*)d_in[28];
    const float* clsw = (const float*)d_in[29];

    float *bufA, *bufB, *xn, *xnT, *tmp, *U, *sa, *sb, *bias2, *wpT, *wwT;
    uint32_t *w1, *w2, *h1A, *h2A, *h1B, *h2B;
    cudaGetSymbolAddress((void**)&bufA,  g_bufA);
    cudaGetSymbolAddress((void**)&bufB,  g_bufB);
    cudaGetSymbolAddress((void**)&xn,    g_xn);
    cudaGetSymbolAddress((void**)&xnT,   g_xnT);
    cudaGetSymbolAddress((void**)&tmp,   g_tmp);
    cudaGetSymbolAddress((void**)&U,     g_U);
    cudaGetSymbolAddress((void**)&sa,    g_sa);
    cudaGetSymbolAddress((void**)&sb,    g_sb);
    cudaGetSymbolAddress((void**)&w1,    g_w1);
    cudaGetSymbolAddress((void**)&w2,    g_w2);
    cudaGetSymbolAddress((void**)&bias2, g_bias2);
    cudaGetSymbolAddress((void**)&h1A,   g_h1A);
    cudaGetSymbolAddress((void**)&h2A,   g_h2A);
    cudaGetSymbolAddress((void**)&h1B,   g_h1B);
    cudaGetSymbolAddress((void**)&h2B,   g_h2B);
    cudaGetSymbolAddress((void**)&wpT,   g_wpT);
    cudaGetSymbolAddress((void**)&wwT,   g_wwT);

    cudaFuncSetAttribute(resconv_mma_kernel,
                         cudaFuncAttributeMaxDynamicSharedMemorySize, RC_WORDS*4);
    cudaFuncSetAttribute(mma_gemm_kernel,
                         cudaFuncAttributeMaxDynamicSharedMemorySize, 2*GBUF*4);
    cudaFuncSetAttribute(sru2_kernel<4>,
                         cudaFuncAttributeMaxDynamicSharedMemorySize, 65536);
    cudaFuncSetAttribute(sru2_kernel<3>,
                         cudaFuncAttributeMaxDynamicSharedMemorySize, 65536);

    // ---- all weight prep, hoisted to graph front ----
    prep_conv_all_kernel<<<dim3(5, 6), 1024>>>(rc1w, rc1b, rb1g, rb1b, rb1m, rb1v,
                                               rc2w, rc2b, rb2g, rb2b, rb2m, rb2v,
                                               w1, w2, bias2);
    trT_kernel<<<dim3(8, 64),  dim3(32, 8)>>>(wproj0, wpT, 2048, 256);
    trT_kernel<<<dim3(128, 8), dim3(32, 8)>>>(w0, wwT, 256, 4096);
    for (int i = 0; i < 3; i++) {
        trT_kernel<<<dim3(8, 32), dim3(32, 8)>>>(wproj + (size_t)i*1024*256,
                                                 wpT + 524288 + i*262144, 1024, 256);
        trT_kernel<<<dim3(96, 8), dim3(32, 8)>>>(w + (size_t)i*256*3072,
                                                 wwT + 1048576 + i*786432, 256, 3072);
    }

    // ---- conv front-end ----
    conv0_kernel<<<dim3(4, 64, 16), 256>>>(x, conv0_w, conv0_b, bufA, h1A, h2A);

    dim3 rcgrid(8, 64, 16);
    for (int i = 0; i < 3; i++) {
        resconv_mma_kernel<<<rcgrid, 256, RC_WORDS*4>>>(h1A, h2A,
            w1 + (2*i)*5760, w2 + (2*i)*5760, bias2 + (2*i)*32,
            nullptr, bufB, h1B, h2B);
        resconv_mma_kernel<<<rcgrid, 256, RC_WORDS*4>>>(h1B, h2B,
            w1 + (2*i+1)*5760, w2 + (2*i+1)*5760, bias2 + (2*i+1)*32,
            bufA, bufA, h1A, h2A);
    }

    // ---- transpose+LN(2048) ----
    transpose_ln_kernel<<<dim3(1024, 16), 256>>>(bufA, ln0g, ln0b, xnT);

    // ---- SRU layer 0 (k=4) ----
    mma_gemm_kernel<<<dim3(2, 128), 256, 2*GBUF*4>>>(xnT, wpT, tmp, NROWS, 256, 2048, 1);
    mma_gemm_kernel<<<dim3(32, 128), 256, 2*GBUF*4>>>(tmp, wwT, U, NROWS, 4096, 256, 0);
    sru2_kernel<4><<<64, 256, 65536>>>(U, xn, vc0, bias0, sa);

    // ---- SRU layers 1-3 (k=3) ----
    float* cur = sa;
    float* nxt = sb;
    for (int i = 0; i < 3; i++) {
        ln_kernel<<<NROWS, 256>>>(cur, lng + i*1024, lnb + i*1024, xn, xnT);
        mma_gemm_kernel<<<dim3(2, 128), 256, 2*GBUF*4>>>(xnT, wpT + 524288 + i*262144,
                                                         tmp, NROWS, 256, 1024, 1);
        mma_gemm_kernel<<<dim3(24, 128), 256, 2*GBUF*4>>>(tmp, wwT + 1048576 + i*786432,
                                                          U, NROWS, 3072, 256, 0);
        sru2_kernel<3><<<64, 256, 65536>>>(U, xn, vc + i*2048, bias + i*2048, nxt);
        float* t2 = cur; cur = nxt; nxt = t2;
    }

    // ---- final LN + classifier ----
    final_kernel<<<NROWS, 256>>>(cur, clng, clnb, clsw, (float*)d_out);
}